// round 8
// baseline (speedup 1.0000x reference)
#include <cuda_runtime.h>
#include <math.h>
#include <stdint.h>

#define T 11
#define N_ENT 100000
#define N_TX 100000
#define D 128
#define E_EDGES 500000
#define F_TX 394
#define COMB_K 1802
#define COMB_STRIDE 1824
#define NEG_SLOPE 0.2f
#define LN_EPS 1e-5f

#define SCAN_BLK 1024
#define NBLK_SCAN ((N_ENT + SCAN_BLK - 1) / SCAN_BLK)   /* 98 */

// ---------------- scratch (device globals; no allocs allowed) ----------------
__device__ float g_xw[(size_t)N_ENT * D];        // per-type (reused across types)
__device__ float g_as[N_ENT];
__device__ float g_ad[N_ENT];
__device__ float g_h[(size_t)N_ENT * D];         // per-type
__device__ float g_comb[(size_t)N_TX * COMB_STRIDE];   // [msgs 1408 | tx 394 | pad 22]
__device__ float g_h1[(size_t)N_TX * D];

// pre-split tf32 weights
__device__ uint32_t g_lwh[128 * 128], g_lwl[128 * 128];
__device__ uint32_t g_w1h[COMB_STRIDE * 128], g_w1l[COMB_STRIDE * 128];  // k-remapped, padded

__device__ int g_cnt[T * N_ENT];
__device__ int g_off[T * N_ENT];
__device__ int g_cur[T * N_ENT];
__device__ int g_csr[(size_t)T * E_EDGES];
__device__ int g_blksum[T * NBLK_SCAN];

// ---------------- helpers ----------------
__device__ __forceinline__ float leaky(float e) { return (e > 0.f) ? e : e * NEG_SLOPE; }

#define FMA4(ACC, S, B) \
    (ACC).x += (S) * (B).x; (ACC).y += (S) * (B).y; \
    (ACC).z += (S) * (B).z; (ACC).w += (S) * (B).w;

__device__ __forceinline__ void cp16(uint32_t s, const void* g) {
    asm volatile("cp.async.cg.shared.global [%0], [%1], 16;" :: "r"(s), "l"(g));
}
#define CP_COMMIT asm volatile("cp.async.commit_group;")
#define CP_WAIT0  asm volatile("cp.async.wait_group 0;")

__device__ __forceinline__ void mma8(float* c, const uint32_t* a, uint32_t b0, uint32_t b1) {
    asm volatile(
        "mma.sync.aligned.m16n8k8.row.col.f32.tf32.tf32.f32 "
        "{%0,%1,%2,%3}, {%4,%5,%6,%7}, {%8,%9}, {%0,%1,%2,%3};"
        : "+f"(c[0]), "+f"(c[1]), "+f"(c[2]), "+f"(c[3])
        : "r"(a[0]), "r"(a[1]), "r"(a[2]), "r"(a[3]), "r"(b0), "r"(b1));
}

__device__ __forceinline__ uint32_t f2tf(float x) {
    uint32_t r;
    asm("cvt.rna.tf32.f32 %0, %1;" : "=r"(r) : "f"(x));
    return r;
}
__device__ __forceinline__ void tfsplit(float x, uint32_t& hi, uint32_t& lo) {
    hi = f2tf(x);
    lo = f2tf(x - __uint_as_float(hi));
}

// ================= weight splitting (once) =================
__global__ void k_split_w(const float* __restrict__ W, const float* __restrict__ w1) {
    int i = blockIdx.x * blockDim.x + threadIdx.x;
    if (i < 128 * 128) {
        uint32_t h, l;
        tfsplit(W[i], h, l);
        g_lwh[i] = h; g_lwl[i] = l;
    }
    if (i < COMB_STRIDE * 128) {
        int ck = i >> 7, c = i & 127;
        float v = 0.f;
        if (ck < 1408)            v = w1[(size_t)(394 + ck) * 128 + c];
        else if (ck < COMB_K)     v = w1[(size_t)(ck - 1408) * 128 + c];
        uint32_t h, l;
        tfsplit(v, h, l);
        g_w1h[i] = h; g_w1l[i] = l;
    }
}

// ================= CSR build =================
__global__ void k_zero_cnt() {
    int i = blockIdx.x * blockDim.x + threadIdx.x;
    if (i < T * N_ENT) g_cnt[i] = 0;
}
__global__ void k_hist(const int* __restrict__ dst) {
    int t = blockIdx.y;
    int i = blockIdx.x * blockDim.x + threadIdx.x;
    if (i < E_EDGES) atomicAdd(&g_cnt[t * N_ENT + dst[(size_t)t * E_EDGES + i]], 1);
}
__global__ void k_scan1() {
    __shared__ int s[SCAN_BLK];
    int t = blockIdx.y, tid = threadIdx.x;
    int idx = blockIdx.x * SCAN_BLK + tid;
    int v = (idx < N_ENT) ? g_cnt[t * N_ENT + idx] : 0;
    s[tid] = v;
    __syncthreads();
#pragma unroll
    for (int off = 1; off < SCAN_BLK; off <<= 1) {
        int y = (tid >= off) ? s[tid - off] : 0;
        __syncthreads();
        s[tid] += y;
        __syncthreads();
    }
    if (idx < N_ENT) g_off[t * N_ENT + idx] = s[tid] - v;
    if (tid == SCAN_BLK - 1) g_blksum[t * NBLK_SCAN + blockIdx.x] = s[tid];
}
__global__ void k_scan2() {
    int t = blockIdx.x;
    if (threadIdx.x == 0) {
        int run = 0;
        for (int b = 0; b < NBLK_SCAN; b++) {
            int v = g_blksum[t * NBLK_SCAN + b];
            g_blksum[t * NBLK_SCAN + b] = run;
            run += v;
        }
    }
}
__global__ void k_scan3() {
    int t = blockIdx.y;
    int idx = blockIdx.x * SCAN_BLK + threadIdx.x;
    if (idx < N_ENT) {
        int v = g_off[t * N_ENT + idx] + g_blksum[t * NBLK_SCAN + blockIdx.x];
        g_off[t * N_ENT + idx] = v;
        g_cur[t * N_ENT + idx] = v;
    }
}
__global__ void k_fill(const int* __restrict__ src, const int* __restrict__ dst) {
    int t = blockIdx.y;
    int i = blockIdx.x * blockDim.x + threadIdx.x;
    if (i < E_EDGES) {
        int d = dst[(size_t)t * E_EDGES + i];
        int pos = atomicAdd(&g_cur[t * N_ENT + d], 1);
        g_csr[(size_t)t * E_EDGES + pos] = src[(size_t)t * E_EDGES + i];
    }
}

// ================= copy tx into combined buffer =================
__global__ void k_copytx(const float* __restrict__ tx) {
    int r = blockIdx.x * 8 + (threadIdx.x >> 5);
    if (r >= N_TX) return;
    int lane = threadIdx.x & 31;
    float* drow = g_comb + (size_t)r * COMB_STRIDE + 1408;
    const float* srow = tx + (size_t)r * F_TX;
    for (int c = lane; c < F_TX; c += 32) drow[c] = srow[c];
    int p = F_TX + lane;
    if (p < COMB_STRIDE - 1408) drow[p] = 0.f;
}

// ================= GEMM1 (3xTF32 mma, pre-split B): xw = emb[idx] @ W ; a_s, a_d =================
#define SA1 132
#define SB1 136
__global__ __launch_bounds__(256, 1) void k_gemm1(
    int t, const float* __restrict__ emb, const int* __restrict__ eidx,
    const float* __restrict__ att_s, const float* __restrict__ att_d) {
    extern __shared__ float sm[];
    float* As = sm;                                    // [128][132] floats
    uint32_t* Bh = (uint32_t*)(sm + 128 * SA1);        // [128][136] u32
    uint32_t* Bl = (uint32_t*)(sm + 128 * SA1 + 128 * SB1);
    const float* embt = emb + (size_t)t * N_ENT * D;
    const int* idxt = eidx + (size_t)t * N_ENT;
    int tid = threadIdx.x;
    int bm = blockIdx.x * 128;
    uint32_t sbase = (uint32_t)__cvta_generic_to_shared(sm);
    uint32_t bhbase = sbase + (uint32_t)(128 * SA1) * 4;
    uint32_t blbase = bhbase + (uint32_t)(128 * SB1) * 4;

#pragma unroll
    for (int i = 0; i < 16; i++) {      // stage Bh/Bl (pre-split lin_w)
        int l = tid + i * 256;
        int row = l >> 5, c4 = l & 31;
        cp16(bhbase + (uint32_t)(row * SB1 + 4 * c4) * 4, g_lwh + row * 128 + 4 * c4);
        cp16(blbase + (uint32_t)(row * SB1 + 4 * c4) * 4, g_lwl + row * 128 + 4 * c4);
    }
#pragma unroll
    for (int i = 0; i < 16; i++) {      // stage A (gathered rows)
        int l = tid + i * 256;
        int row = l >> 5, c4 = l & 31;
        int rg = bm + row;
        int srcr = (rg < N_ENT) ? idxt[rg] : 0;
        cp16(sbase + (uint32_t)(row * SA1 + 4 * c4) * 4, embt + (size_t)srcr * D + 4 * c4);
    }
    CP_COMMIT; CP_WAIT0;
    __syncthreads();

    int lane = tid & 31, wid = tid >> 5;
    int wm = (wid & 3) * 32, wn = (wid >> 2) * 64;
    int l4 = lane >> 2, lq = lane & 3;
    float acc[2][8][4];
#pragma unroll
    for (int mt = 0; mt < 2; mt++)
#pragma unroll
        for (int nt = 0; nt < 8; nt++)
#pragma unroll
            for (int q = 0; q < 4; q++) acc[mt][nt][q] = 0.f;

    for (int k0 = 0; k0 < 128; k0 += 8) {
        uint32_t ah[2][4], al[2][4];
#pragma unroll
        for (int mt = 0; mt < 2; mt++) {
            int r = wm + mt * 16 + l4;
            tfsplit(As[r * SA1 + k0 + lq],           ah[mt][0], al[mt][0]);
            tfsplit(As[(r + 8) * SA1 + k0 + lq],     ah[mt][1], al[mt][1]);
            tfsplit(As[r * SA1 + k0 + lq + 4],       ah[mt][2], al[mt][2]);
            tfsplit(As[(r + 8) * SA1 + k0 + lq + 4], ah[mt][3], al[mt][3]);
        }
#pragma unroll
        for (int nt = 0; nt < 8; nt++) {
            int cb = wn + nt * 8 + l4;
            uint32_t b0h = Bh[(k0 + lq) * SB1 + cb];
            uint32_t b1h = Bh[(k0 + lq + 4) * SB1 + cb];
            uint32_t b0l = Bl[(k0 + lq) * SB1 + cb];
            uint32_t b1l = Bl[(k0 + lq + 4) * SB1 + cb];
#pragma unroll
            for (int mt = 0; mt < 2; mt++) {
                mma8(acc[mt][nt], ah[mt], b0h, b1h);
                mma8(acc[mt][nt], al[mt], b0h, b1h);
                mma8(acc[mt][nt], ah[mt], b0l, b1l);
            }
        }
    }
    __syncthreads();
    float* Cs = As;   // reuse
#pragma unroll
    for (int mt = 0; mt < 2; mt++)
#pragma unroll
        for (int nt = 0; nt < 8; nt++) {
            int r = wm + mt * 16 + l4;
            int c = wn + nt * 8 + 2 * lq;
            *(float2*)&Cs[r * SA1 + c] = make_float2(acc[mt][nt][0], acc[mt][nt][1]);
            *(float2*)&Cs[(r + 8) * SA1 + c] = make_float2(acc[mt][nt][2], acc[mt][nt][3]);
        }
    __syncthreads();

    float4 aS = ((const float4*)att_s)[lane];
    float4 aD = ((const float4*)att_d)[lane];
    for (int i = 0; i < 16; i++) {
        int row = wid * 16 + i;
        int rg = bm + row;
        if (rg >= N_ENT) break;
        float4 v = *(float4*)&Cs[row * SA1 + 4 * lane];
        ((float4*)(g_xw + (size_t)rg * D))[lane] = v;
        float s = v.x * aS.x + v.y * aS.y + v.z * aS.z + v.w * aS.w;
        float d = v.x * aD.x + v.y * aD.y + v.z * aD.z + v.w * aD.w;
#pragma unroll
        for (int off = 16; off; off >>= 1) {
            s += __shfl_xor_sync(0xffffffffu, s, off);
            d += __shfl_xor_sync(0xffffffffu, d, off);
        }
        if (lane == 0) { g_as[rg] = s; g_ad[rg] = d; }
    }
}

// ================= fused GAT: single-pass softmax+aggregate + bias + LN =================
__global__ void k_gat(int t, const float* __restrict__ conv_bias,
                      const float* __restrict__ gamma_all, const float* __restrict__ beta_all) {
    int dn = blockIdx.x * 8 + (threadIdx.x >> 5);
    if (dn >= N_ENT) return;
    int lane = threadIdx.x & 31;
    const float* asv = g_as;
    float ad = g_ad[dn];
    int off0 = g_off[t * N_ENT + dn];
    int off1 = (dn + 1 < N_ENT) ? g_off[t * N_ENT + dn + 1] : E_EDGES;
    const int* csr = g_csr + (size_t)t * E_EDGES;
    const float* xw = g_xw;

    float ex_self = __expf(leaky(asv[dn] + ad));
    float wsum = ex_self;
    float4 vs = ((const float4*)(xw + (size_t)dn * D))[lane];
    float4 acc = make_float4(ex_self * vs.x, ex_self * vs.y, ex_self * vs.z, ex_self * vs.w);

    for (int j = off0; j < off1; j++) {
        int s = csr[j];
        float e = __expf(leaky(asv[s] + ad));
        float4 v = ((const float4*)(xw + (size_t)s * D))[lane];
        FMA4(acc, e, v);
        wsum += e;
    }
    float inv = 1.f / (wsum + 1e-16f);
    acc.x *= inv; acc.y *= inv; acc.z *= inv; acc.w *= inv;

    float4 cb = ((const float4*)conv_bias)[lane];
    acc.x += cb.x; acc.y += cb.y; acc.z += cb.z; acc.w += cb.w;
    float sum = acc.x + acc.y + acc.z + acc.w;
#pragma unroll
    for (int off = 16; off; off >>= 1) sum += __shfl_xor_sync(0xffffffffu, sum, off);
    float mu = sum * (1.f / D);
    float4 dd = make_float4(acc.x - mu, acc.y - mu, acc.z - mu, acc.w - mu);
    float sq = dd.x * dd.x + dd.y * dd.y + dd.z * dd.z + dd.w * dd.w;
#pragma unroll
    for (int off = 16; off; off >>= 1) sq += __shfl_xor_sync(0xffffffffu, sq, off);
    float invs = rsqrtf(sq * (1.f / D) + LN_EPS);
    float4 gm = ((const float4*)(gamma_all + t * D))[lane];
    float4 bt = ((const float4*)(beta_all + t * D))[lane];
    float4 h;
    h.x = dd.x * invs * gm.x + bt.x;
    h.y = dd.y * invs * gm.y + bt.y;
    h.z = dd.z * invs * gm.z + bt.z;
    h.w = dd.w * invs * gm.w + bt.w;
    ((float4*)(g_h + (size_t)dn * D))[lane] = h;
}

// ================= msg gather into combined buffer =================
__global__ void k_msg(int t) {
    int dn = blockIdx.x * 8 + (threadIdx.x >> 5);
    if (dn >= N_TX) return;
    int lane = threadIdx.x & 31;
    int off0 = g_off[t * N_ENT + dn];
    int off1 = (dn + 1 < N_ENT) ? g_off[t * N_ENT + dn + 1] : E_EDGES;
    const int* csr = g_csr + (size_t)t * E_EDGES;
    const float* h = g_h;
    float4 acc = make_float4(0.f, 0.f, 0.f, 0.f);
    for (int j = off0; j < off1; j++) {
        float4 v = ((const float4*)(h + (size_t)csr[j] * D))[lane];
        acc.x += v.x; acc.y += v.y; acc.z += v.z; acc.w += v.w;
    }
    ((float4*)(g_comb + (size_t)dn * COMB_STRIDE + t * D))[lane] = acc;
}

// ================= classifier layer 1 (3xTF32 mma, pre-split B, double-buffered) =================
#define SA2 36
#define SB2 136
#define NIT 57   /* 1824 / 32 */
__device__ __forceinline__ void h1_stage(uint32_t abase, uint32_t bhbase, uint32_t blbase,
                                         int kc, int bm, int tid) {
#pragma unroll
    for (int i = 0; i < 4; i++) {       // A: 128 rows x 8 float4
        int l = tid + i * 256;
        int row = l >> 3, c4 = l & 7;
        int rg = bm + row;
        if (rg >= N_TX) rg = 0;
        cp16(abase + (uint32_t)(row * SA2 + 4 * c4) * 4,
             g_comb + (size_t)rg * COMB_STRIDE + kc + 4 * c4);
    }
#pragma unroll
    for (int i = 0; i < 4; i++) {       // Bh/Bl: 32 k x 32 float4 each (linear, padded)
        int l = tid + i * 256;
        int kk = l >> 5, c4 = l & 31;
        cp16(bhbase + (uint32_t)(kk * SB2 + 4 * c4) * 4,
             g_w1h + (size_t)(kc + kk) * 128 + 4 * c4);
        cp16(blbase + (uint32_t)(kk * SB2 + 4 * c4) * 4,
             g_w1l + (size_t)(kc + kk) * 128 + 4 * c4);
    }
}

#define H1_A_WORDS   (128 * SA2)
#define H1_B_WORDS   (32 * SB2)
#define H1_SMEM_W    (2 * H1_A_WORDS + 4 * H1_B_WORDS)

__global__ __launch_bounds__(256, 2) void k_h1(const float* __restrict__ b1) {
    extern __shared__ float sm[];
    int tid = threadIdx.x;
    int bm = blockIdx.x * 128;
    uint32_t sbase = (uint32_t)__cvta_generic_to_shared(sm);
    uint32_t aB[2]  = {sbase, sbase + (uint32_t)H1_A_WORDS * 4};
    uint32_t bhB[2] = {sbase + (uint32_t)(2 * H1_A_WORDS) * 4,
                       sbase + (uint32_t)(2 * H1_A_WORDS + H1_B_WORDS) * 4};
    uint32_t blB[2] = {sbase + (uint32_t)(2 * H1_A_WORDS + 2 * H1_B_WORDS) * 4,
                       sbase + (uint32_t)(2 * H1_A_WORDS + 3 * H1_B_WORDS) * 4};
    const float* Ap[2] = {sm, sm + H1_A_WORDS};
    const uint32_t* Bhp[2] = {(const uint32_t*)(sm + 2 * H1_A_WORDS),
                              (const uint32_t*)(sm + 2 * H1_A_WORDS + H1_B_WORDS)};
    const uint32_t* Blp[2] = {(const uint32_t*)(sm + 2 * H1_A_WORDS + 2 * H1_B_WORDS),
                              (const uint32_t*)(sm + 2 * H1_A_WORDS + 3 * H1_B_WORDS)};

    int lane = tid & 31, wid = tid >> 5;
    int wm = (wid & 3) * 32, wn = (wid >> 2) * 64;
    int l4 = lane >> 2, lq = lane & 3;
    float acc[2][8][4];
#pragma unroll
    for (int mt = 0; mt < 2; mt++)
#pragma unroll
        for (int nt = 0; nt < 8; nt++)
#pragma unroll
            for (int q = 0; q < 4; q++) acc[mt][nt][q] = 0.f;

    h1_stage(aB[0], bhB[0], blB[0], 0, bm, tid);
    CP_COMMIT;

    for (int it = 0; it < NIT; it++) {
        int cur = it & 1;
        CP_WAIT0;
        __syncthreads();
        if (it + 1 < NIT) {
            h1_stage(aB[1 - cur], bhB[1 - cur], blB[1 - cur], (it + 1) * 32, bm, tid);
            CP_COMMIT;
        }
        const float* Af = Ap[cur];
        const uint32_t* Bhf = Bhp[cur];
        const uint32_t* Blf = Blp[cur];
#pragma unroll
        for (int ks = 0; ks < 4; ks++) {
            int k0 = ks * 8;
            uint32_t ah[2][4], al[2][4];
#pragma unroll
            for (int mt = 0; mt < 2; mt++) {
                int r = wm + mt * 16 + l4;
                tfsplit(Af[r * SA2 + k0 + lq],           ah[mt][0], al[mt][0]);
                tfsplit(Af[(r + 8) * SA2 + k0 + lq],     ah[mt][1], al[mt][1]);
                tfsplit(Af[r * SA2 + k0 + lq + 4],       ah[mt][2], al[mt][2]);
                tfsplit(Af[(r + 8) * SA2 + k0 + lq + 4], ah[mt][3], al[mt][3]);
            }
#pragma unroll
            for (int nt = 0; nt < 8; nt++) {
                int cb = wn + nt * 8 + l4;
                uint32_t b0h = Bhf[(k0 + lq) * SB2 + cb];
                uint32_t b1h = Bhf[(k0 + lq + 4) * SB2 + cb];
                uint32_t b0l = Blf[(k0 + lq) * SB2 + cb];
                uint32_t b1l = Blf[(k0 + lq + 4) * SB2 + cb];
#pragma unroll
                for (int mt = 0; mt < 2; mt++) {
                    mma8(acc[mt][nt], ah[mt], b0h, b1h);
                    mma8(acc[mt][nt], al[mt], b0h, b1h);
                    mma8(acc[mt][nt], ah[mt], b0l, b1l);
                }
            }
        }
        __syncthreads();
    }

#pragma unroll
    for (int mt = 0; mt < 2; mt++)
#pragma unroll
        for (int nt = 0; nt < 8; nt++) {
            int r = bm + wm + mt * 16 + l4;
            int c = wn + nt * 8 + 2 * lq;
            float2 bb = *(const float2*)(b1 + c);
            if (r < N_TX)
                *(float2*)&g_h1[(size_t)r * D + c] =
                    make_float2(fmaxf(acc[mt][nt][0] + bb.x, 0.f),
                                fmaxf(acc[mt][nt][1] + bb.y, 0.f));
            if (r + 8 < N_TX)
                *(float2*)&g_h1[(size_t)(r + 8) * D + c] =
                    make_float2(fmaxf(acc[mt][nt][2] + bb.x, 0.f),
                                fmaxf(acc[mt][nt][3] + bb.y, 0.f));
        }
}

// ================= fused classifier layers 2+3 =================
__global__ void k_h23(const float* __restrict__ w2, const float* __restrict__ b2,
                      const float* __restrict__ w3, const float* __restrict__ b3,
                      float* __restrict__ out) {
    __shared__ float Ws[128 * 64];
    __shared__ float w3s[64];
    int tid = threadIdx.x;
#pragma unroll
    for (int i = 0; i < 8; i++)
        ((float4*)Ws)[tid + i * 256] = ((const float4*)w2)[tid + i * 256];
    if (tid < 64) w3s[tid] = w3[tid];
    __syncthreads();
    int lane = tid & 31, w = tid >> 5;
    for (int rr = 0; rr < 4; rr++) {
        int r = blockIdx.x * 32 + rr * 8 + w;
        if (r >= N_TX) return;
        float4 x = ((const float4*)(g_h1 + (size_t)r * D))[lane];
        float xa[4] = {x.x, x.y, x.z, x.w};
        float a0 = 0.f, a1 = 0.f;
#pragma unroll
        for (int k = 0; k < 128; k++) {
            float xk = __shfl_sync(0xffffffffu, xa[k & 3], k >> 2);
            float2 wv = *(const float2*)&Ws[k * 64 + lane * 2];
            a0 += xk * wv.x;
            a1 += xk * wv.y;
        }
        float2 bb = *(const float2*)&b2[lane * 2];
        float h0 = fmaxf(a0 + bb.x, 0.f);
        float h1v = fmaxf(a1 + bb.y, 0.f);
        float v = h0 * w3s[lane * 2] + h1v * w3s[lane * 2 + 1];
#pragma unroll
        for (int off = 16; off; off >>= 1) v += __shfl_xor_sync(0xffffffffu, v, off);
        if (lane == 0) out[r] = v + b3[0];
    }
}

// ================= launcher =================
extern "C" void kernel_launch(void* const* d_in, const int* in_sizes, int n_in,
                              void* d_out, int out_size) {
    const float* tx_x      = (const float*)d_in[0];
    const float* emb       = (const float*)d_in[1];
    const float* lin_w     = (const float*)d_in[2];
    const float* att_src   = (const float*)d_in[3];
    const float* att_dst   = (const float*)d_in[4];
    const float* conv_bias = (const float*)d_in[5];
    const float* ln_gamma  = (const float*)d_in[6];
    const float* ln_beta   = (const float*)d_in[7];
    const float* w1        = (const float*)d_in[8];
    const float* b1        = (const float*)d_in[9];
    const float* w2        = (const float*)d_in[10];
    const float* b2        = (const float*)d_in[11];
    const float* w3        = (const float*)d_in[12];
    const float* b3        = (const float*)d_in[13];
    const int* entity_idx  = (const int*)d_in[14];
    const int* edge_src    = (const int*)d_in[15];
    const int* edge_dst    = (const int*)d_in[16];
    float* out = (float*)d_out;

    cudaFuncSetAttribute(k_gemm1, cudaFuncAttributeMaxDynamicSharedMemorySize,
                         (128 * SA1 + 2 * 128 * SB1) * 4);
    cudaFuncSetAttribute(k_h1, cudaFuncAttributeMaxDynamicSharedMemorySize,
                         H1_SMEM_W * 4);

    // ---- weight splits (once per launch; deterministic) ----
    k_split_w<<<(COMB_STRIDE * 128 + 255) / 256, 256>>>(lin_w, w1);

    // ---- CSR build ----
    k_zero_cnt<<<(T * N_ENT + 255) / 256, 256>>>();
    { dim3 g((E_EDGES + 255) / 256, T); k_hist<<<g, 256>>>(edge_dst); }
    { dim3 g(NBLK_SCAN, T); k_scan1<<<g, SCAN_BLK>>>(); }
    k_scan2<<<T, 32>>>();
    { dim3 g(NBLK_SCAN, T); k_scan3<<<g, SCAN_BLK>>>(); }
    { dim3 g((E_EDGES + 255) / 256, T); k_fill<<<g, 256>>>(edge_src, edge_dst); }

    // ---- tx into combined buffer (independent) ----
    k_copytx<<<(N_TX + 7) / 8, 256>>>(tx_x);

    // ---- per-type interleaved pipeline: producer->consumer L2 locality ----
    for (int t = 0; t < T; t++) {
        k_gemm1<<<(N_ENT + 127) / 128, 256, (128 * SA1 + 2 * 128 * SB1) * 4>>>(
            t, emb, entity_idx, att_src, att_dst);
        k_gat<<<(N_ENT + 7) / 8, 256>>>(t, conv_bias, ln_gamma, ln_beta);
        k_msg<<<(N_TX + 7) / 8, 256>>>(t);
    }

    // ---- classifier ----
    k_h1<<<(N_TX + 127) / 128, 256, H1_SMEM_W * 4>>>(b1);
    k_h23<<<(N_TX + 31) / 32, 256>>>(w2, b2, w3, b3, out);
}

// round 9
// speedup vs baseline: 1.0900x; 1.0900x over previous
#include <cuda_runtime.h>
#include <cuda_fp16.h>
#include <math.h>
#include <stdint.h>

#define T 11
#define N_ENT 100000
#define N_TX 100000
#define D 128
#define E_EDGES 500000
#define F_TX 394
#define COMB_K 1802
#define COMB_STRIDE 1824
#define NEG_SLOPE 0.2f
#define LN_EPS 1e-5f

#define SCAN_BLK 1024
#define NBLK_SCAN ((N_ENT + SCAN_BLK - 1) / SCAN_BLK)   /* 98 */

// ---------------- scratch (device globals; no allocs allowed) ----------------
__device__ __half g_xw[(size_t)T * N_ENT * D];   // fp16 to halve gather bytes
__device__ float g_as[T * N_ENT];
__device__ float g_ad[T * N_ENT];
__device__ __half g_h[(size_t)T * N_ENT * D];    // fp16
__device__ float g_comb[(size_t)N_TX * COMB_STRIDE];   // [msgs 1408 | tx 394 | pad 22]
__device__ float g_h1[(size_t)N_TX * D];

// pre-split tf32 weights
__device__ uint32_t g_lwh[128 * 128], g_lwl[128 * 128];
__device__ uint32_t g_w1h[COMB_STRIDE * 128], g_w1l[COMB_STRIDE * 128];  // k-remapped, padded

__device__ int g_cnt[T * N_ENT];
__device__ int g_off[T * N_ENT];
__device__ int g_cur[T * N_ENT];
__device__ int g_csr[(size_t)T * E_EDGES];
__device__ int g_blksum[T * NBLK_SCAN];

// ---------------- helpers ----------------
__device__ __forceinline__ float leaky(float e) { return (e > 0.f) ? e : e * NEG_SLOPE; }

#define FMA4(ACC, S, B) \
    (ACC).x += (S) * (B).x; (ACC).y += (S) * (B).y; \
    (ACC).z += (S) * (B).z; (ACC).w += (S) * (B).w;

// load 4 halves (8 bytes) at column 4*lane of a row, convert to float4
__device__ __forceinline__ float4 ld_half4(const __half* row, int lane) {
    uint2 p = ((const uint2*)row)[lane];
    float2 lo = __half22float2(*(__half2*)&p.x);
    float2 hi = __half22float2(*(__half2*)&p.y);
    return make_float4(lo.x, lo.y, hi.x, hi.y);
}
__device__ __forceinline__ void st_half4(__half* row, int lane, float4 v) {
    __half2 h0 = __floats2half2_rn(v.x, v.y);
    __half2 h1 = __floats2half2_rn(v.z, v.w);
    uint2 p;
    p.x = *(uint32_t*)&h0;
    p.y = *(uint32_t*)&h1;
    ((uint2*)row)[lane] = p;
}

__device__ __forceinline__ void cp16(uint32_t s, const void* g) {
    asm volatile("cp.async.cg.shared.global [%0], [%1], 16;" :: "r"(s), "l"(g));
}
#define CP_COMMIT asm volatile("cp.async.commit_group;")
#define CP_WAIT0  asm volatile("cp.async.wait_group 0;")

__device__ __forceinline__ void mma8(float* c, const uint32_t* a, uint32_t b0, uint32_t b1) {
    asm volatile(
        "mma.sync.aligned.m16n8k8.row.col.f32.tf32.tf32.f32 "
        "{%0,%1,%2,%3}, {%4,%5,%6,%7}, {%8,%9}, {%0,%1,%2,%3};"
        : "+f"(c[0]), "+f"(c[1]), "+f"(c[2]), "+f"(c[3])
        : "r"(a[0]), "r"(a[1]), "r"(a[2]), "r"(a[3]), "r"(b0), "r"(b1));
}

__device__ __forceinline__ uint32_t f2tf(float x) {
    uint32_t r;
    asm("cvt.rna.tf32.f32 %0, %1;" : "=r"(r) : "f"(x));
    return r;
}
__device__ __forceinline__ void tfsplit(float x, uint32_t& hi, uint32_t& lo) {
    hi = f2tf(x);
    lo = f2tf(x - __uint_as_float(hi));
}

// ================= weight splitting (once) =================
__global__ void k_split_w(const float* __restrict__ W, const float* __restrict__ w1) {
    int i = blockIdx.x * blockDim.x + threadIdx.x;
    if (i < 128 * 128) {
        uint32_t h, l;
        tfsplit(W[i], h, l);
        g_lwh[i] = h; g_lwl[i] = l;
    }
    if (i < COMB_STRIDE * 128) {
        int ck = i >> 7, c = i & 127;
        float v = 0.f;
        if (ck < 1408)            v = w1[(size_t)(394 + ck) * 128 + c];
        else if (ck < COMB_K)     v = w1[(size_t)(ck - 1408) * 128 + c];
        uint32_t h, l;
        tfsplit(v, h, l);
        g_w1h[i] = h; g_w1l[i] = l;
    }
}

// ================= CSR build =================
__global__ void k_zero_cnt() {
    int i = blockIdx.x * blockDim.x + threadIdx.x;
    if (i < T * N_ENT) g_cnt[i] = 0;
}
__global__ void k_hist(const int* __restrict__ dst) {
    int t = blockIdx.y;
    int i = blockIdx.x * blockDim.x + threadIdx.x;
    if (i < E_EDGES) atomicAdd(&g_cnt[t * N_ENT + dst[(size_t)t * E_EDGES + i]], 1);
}
__global__ void k_scan1() {
    __shared__ int s[SCAN_BLK];
    int t = blockIdx.y, tid = threadIdx.x;
    int idx = blockIdx.x * SCAN_BLK + tid;
    int v = (idx < N_ENT) ? g_cnt[t * N_ENT + idx] : 0;
    s[tid] = v;
    __syncthreads();
#pragma unroll
    for (int off = 1; off < SCAN_BLK; off <<= 1) {
        int y = (tid >= off) ? s[tid - off] : 0;
        __syncthreads();
        s[tid] += y;
        __syncthreads();
    }
    if (idx < N_ENT) g_off[t * N_ENT + idx] = s[tid] - v;
    if (tid == SCAN_BLK - 1) g_blksum[t * NBLK_SCAN + blockIdx.x] = s[tid];
}
__global__ void k_scan2() {
    int t = blockIdx.x;
    if (threadIdx.x == 0) {
        int run = 0;
        for (int b = 0; b < NBLK_SCAN; b++) {
            int v = g_blksum[t * NBLK_SCAN + b];
            g_blksum[t * NBLK_SCAN + b] = run;
            run += v;
        }
    }
}
__global__ void k_scan3() {
    int t = blockIdx.y;
    int idx = blockIdx.x * SCAN_BLK + threadIdx.x;
    if (idx < N_ENT) {
        int v = g_off[t * N_ENT + idx] + g_blksum[t * NBLK_SCAN + blockIdx.x];
        g_off[t * N_ENT + idx] = v;
        g_cur[t * N_ENT + idx] = v;
    }
}
__global__ void k_fill(const int* __restrict__ src, const int* __restrict__ dst) {
    int t = blockIdx.y;
    int i = blockIdx.x * blockDim.x + threadIdx.x;
    if (i < E_EDGES) {
        int d = dst[(size_t)t * E_EDGES + i];
        int pos = atomicAdd(&g_cur[t * N_ENT + d], 1);
        g_csr[(size_t)t * E_EDGES + pos] = src[(size_t)t * E_EDGES + i];
    }
}

// ================= copy tx into combined buffer =================
__global__ void k_copytx(const float* __restrict__ tx) {
    int r = blockIdx.x * 8 + (threadIdx.x >> 5);
    if (r >= N_TX) return;
    int lane = threadIdx.x & 31;
    float* drow = g_comb + (size_t)r * COMB_STRIDE + 1408;
    const float* srow = tx + (size_t)r * F_TX;
    for (int c = lane; c < F_TX; c += 32) drow[c] = srow[c];
    int p = F_TX + lane;
    if (p < COMB_STRIDE - 1408) drow[p] = 0.f;
}

// ================= GEMM1 (3xTF32 mma, pre-split B): xw = emb[idx] @ W ; a_s, a_d =================
#define SA1 132
#define SB1 136
__global__ __launch_bounds__(256, 1) void k_gemm1(
    const float* __restrict__ emb, const int* __restrict__ eidx,
    const float* __restrict__ att_s, const float* __restrict__ att_d) {
    extern __shared__ float sm[];
    float* As = sm;                                    // [128][132] floats
    uint32_t* Bh = (uint32_t*)(sm + 128 * SA1);        // [128][136] u32
    uint32_t* Bl = (uint32_t*)(sm + 128 * SA1 + 128 * SB1);
    int t = blockIdx.y;
    const float* embt = emb + (size_t)t * N_ENT * D;
    const int* idxt = eidx + (size_t)t * N_ENT;
    int tid = threadIdx.x;
    int bm = blockIdx.x * 128;
    uint32_t sbase = (uint32_t)__cvta_generic_to_shared(sm);
    uint32_t bhbase = sbase + (uint32_t)(128 * SA1) * 4;
    uint32_t blbase = bhbase + (uint32_t)(128 * SB1) * 4;

#pragma unroll
    for (int i = 0; i < 16; i++) {      // stage Bh/Bl (pre-split lin_w)
        int l = tid + i * 256;
        int row = l >> 5, c4 = l & 31;
        cp16(bhbase + (uint32_t)(row * SB1 + 4 * c4) * 4, g_lwh + row * 128 + 4 * c4);
        cp16(blbase + (uint32_t)(row * SB1 + 4 * c4) * 4, g_lwl + row * 128 + 4 * c4);
    }
#pragma unroll
    for (int i = 0; i < 16; i++) {      // stage A (gathered rows)
        int l = tid + i * 256;
        int row = l >> 5, c4 = l & 31;
        int rg = bm + row;
        int srcr = (rg < N_ENT) ? idxt[rg] : 0;
        cp16(sbase + (uint32_t)(row * SA1 + 4 * c4) * 4, embt + (size_t)srcr * D + 4 * c4);
    }
    CP_COMMIT; CP_WAIT0;
    __syncthreads();

    int lane = tid & 31, wid = tid >> 5;
    int wm = (wid & 3) * 32, wn = (wid >> 2) * 64;
    int l4 = lane >> 2, lq = lane & 3;
    float acc[2][8][4];
#pragma unroll
    for (int mt = 0; mt < 2; mt++)
#pragma unroll
        for (int nt = 0; nt < 8; nt++)
#pragma unroll
            for (int q = 0; q < 4; q++) acc[mt][nt][q] = 0.f;

    for (int k0 = 0; k0 < 128; k0 += 8) {
        uint32_t ah[2][4], al[2][4];
#pragma unroll
        for (int mt = 0; mt < 2; mt++) {
            int r = wm + mt * 16 + l4;
            tfsplit(As[r * SA1 + k0 + lq],           ah[mt][0], al[mt][0]);
            tfsplit(As[(r + 8) * SA1 + k0 + lq],     ah[mt][1], al[mt][1]);
            tfsplit(As[r * SA1 + k0 + lq + 4],       ah[mt][2], al[mt][2]);
            tfsplit(As[(r + 8) * SA1 + k0 + lq + 4], ah[mt][3], al[mt][3]);
        }
#pragma unroll
        for (int nt = 0; nt < 8; nt++) {
            int cb = wn + nt * 8 + l4;
            uint32_t b0h = Bh[(k0 + lq) * SB1 + cb];
            uint32_t b1h = Bh[(k0 + lq + 4) * SB1 + cb];
            uint32_t b0l = Bl[(k0 + lq) * SB1 + cb];
            uint32_t b1l = Bl[(k0 + lq + 4) * SB1 + cb];
#pragma unroll
            for (int mt = 0; mt < 2; mt++) {
                mma8(acc[mt][nt], ah[mt], b0h, b1h);
                mma8(acc[mt][nt], al[mt], b0h, b1h);
                mma8(acc[mt][nt], ah[mt], b0l, b1l);
            }
        }
    }
    __syncthreads();
    float* Cs = As;   // reuse
#pragma unroll
    for (int mt = 0; mt < 2; mt++)
#pragma unroll
        for (int nt = 0; nt < 8; nt++) {
            int r = wm + mt * 16 + l4;
            int c = wn + nt * 8 + 2 * lq;
            *(float2*)&Cs[r * SA1 + c] = make_float2(acc[mt][nt][0], acc[mt][nt][1]);
            *(float2*)&Cs[(r + 8) * SA1 + c] = make_float2(acc[mt][nt][2], acc[mt][nt][3]);
        }
    __syncthreads();

    float4 aS = ((const float4*)att_s)[lane];
    float4 aD = ((const float4*)att_d)[lane];
    for (int i = 0; i < 16; i++) {
        int row = wid * 16 + i;
        int rg = bm + row;
        if (rg >= N_ENT) break;
        float4 v = *(float4*)&Cs[row * SA1 + 4 * lane];
        st_half4(g_xw + ((size_t)t * N_ENT + rg) * D, lane, v);
        float s = v.x * aS.x + v.y * aS.y + v.z * aS.z + v.w * aS.w;
        float d = v.x * aD.x + v.y * aD.y + v.z * aD.z + v.w * aD.w;
#pragma unroll
        for (int off = 16; off; off >>= 1) {
            s += __shfl_xor_sync(0xffffffffu, s, off);
            d += __shfl_xor_sync(0xffffffffu, d, off);
        }
        if (lane == 0) { g_as[t * N_ENT + rg] = s; g_ad[t * N_ENT + rg] = d; }
    }
}

// ================= fused GAT: single-pass softmax+aggregate + bias + LN =================
__global__ void k_gat(const float* __restrict__ conv_bias,
                      const float* __restrict__ gamma_all, const float* __restrict__ beta_all) {
    int t = blockIdx.y;
    int dn = blockIdx.x * 8 + (threadIdx.x >> 5);
    if (dn >= N_ENT) return;
    int lane = threadIdx.x & 31;
    const float* asv = g_as + t * N_ENT;
    float ad = g_ad[t * N_ENT + dn];
    int off0 = g_off[t * N_ENT + dn];
    int off1 = (dn + 1 < N_ENT) ? g_off[t * N_ENT + dn + 1] : E_EDGES;
    const int* csr = g_csr + (size_t)t * E_EDGES;
    const __half* xw = g_xw + (size_t)t * N_ENT * D;

    float ex_self = __expf(leaky(asv[dn] + ad));
    float wsum = ex_self;
    float4 vs = ld_half4(xw + (size_t)dn * D, lane);
    float4 acc = make_float4(ex_self * vs.x, ex_self * vs.y, ex_self * vs.z, ex_self * vs.w);

    for (int j = off0; j < off1; j++) {
        int s = csr[j];
        float e = __expf(leaky(asv[s] + ad));
        float4 v = ld_half4(xw + (size_t)s * D, lane);
        FMA4(acc, e, v);
        wsum += e;
    }
    float inv = 1.f / (wsum + 1e-16f);
    acc.x *= inv; acc.y *= inv; acc.z *= inv; acc.w *= inv;

    float4 cb = ((const float4*)conv_bias)[lane];
    acc.x += cb.x; acc.y += cb.y; acc.z += cb.z; acc.w += cb.w;
    float sum = acc.x + acc.y + acc.z + acc.w;
#pragma unroll
    for (int off = 16; off; off >>= 1) sum += __shfl_xor_sync(0xffffffffu, sum, off);
    float mu = sum * (1.f / D);
    float4 dd = make_float4(acc.x - mu, acc.y - mu, acc.z - mu, acc.w - mu);
    float sq = dd.x * dd.x + dd.y * dd.y + dd.z * dd.z + dd.w * dd.w;
#pragma unroll
    for (int off = 16; off; off >>= 1) sq += __shfl_xor_sync(0xffffffffu, sq, off);
    float invs = rsqrtf(sq * (1.f / D) + LN_EPS);
    float4 gm = ((const float4*)(gamma_all + t * D))[lane];
    float4 bt = ((const float4*)(beta_all + t * D))[lane];
    float4 h;
    h.x = dd.x * invs * gm.x + bt.x;
    h.y = dd.y * invs * gm.y + bt.y;
    h.z = dd.z * invs * gm.z + bt.z;
    h.w = dd.w * invs * gm.w + bt.w;
    st_half4(g_h + ((size_t)t * N_ENT + dn) * D, lane, h);
}

// ================= msg gather into combined buffer =================
__global__ void k_msg() {
    int t = blockIdx.y;
    int dn = blockIdx.x * 8 + (threadIdx.x >> 5);
    if (dn >= N_TX) return;
    int lane = threadIdx.x & 31;
    int off0 = g_off[t * N_ENT + dn];
    int off1 = (dn + 1 < N_ENT) ? g_off[t * N_ENT + dn + 1] : E_EDGES;
    const int* csr = g_csr + (size_t)t * E_EDGES;
    const __half* h = g_h + (size_t)t * N_ENT * D;
    float4 acc = make_float4(0.f, 0.f, 0.f, 0.f);
    for (int j = off0; j < off1; j++) {
        float4 v = ld_half4(h + (size_t)csr[j] * D, lane);
        acc.x += v.x; acc.y += v.y; acc.z += v.z; acc.w += v.w;
    }
    ((float4*)(g_comb + (size_t)dn * COMB_STRIDE + t * D))[lane] = acc;
}

// ================= classifier layer 1 (3xTF32 mma, pre-split B, double-buffered) =================
#define SA2 36
#define SB2 136
#define NIT 57   /* 1824 / 32 */
__device__ __forceinline__ void h1_stage(uint32_t abase, uint32_t bhbase, uint32_t blbase,
                                         int kc, int bm, int tid) {
#pragma unroll
    for (int i = 0; i < 4; i++) {       // A: 128 rows x 8 float4
        int l = tid + i * 256;
        int row = l >> 3, c4 = l & 7;
        int rg = bm + row;
        if (rg >= N_TX) rg = 0;
        cp16(abase + (uint32_t)(row * SA2 + 4 * c4) * 4,
             g_comb + (size_t)rg * COMB_STRIDE + kc + 4 * c4);
    }
#pragma unroll
    for (int i = 0; i < 4; i++) {       // Bh/Bl: 32 k x 32 float4 each (linear, padded)
        int l = tid + i * 256;
        int kk = l >> 5, c4 = l & 31;
        cp16(bhbase + (uint32_t)(kk * SB2 + 4 * c4) * 4,
             g_w1h + (size_t)(kc + kk) * 128 + 4 * c4);
        cp16(blbase + (uint32_t)(kk * SB2 + 4 * c4) * 4,
             g_w1l + (size_t)(kc + kk) * 128 + 4 * c4);
    }
}

#define H1_A_WORDS   (128 * SA2)
#define H1_B_WORDS   (32 * SB2)
#define H1_SMEM_W    (2 * H1_A_WORDS + 4 * H1_B_WORDS)

__global__ __launch_bounds__(256, 2) void k_h1(const float* __restrict__ b1) {
    extern __shared__ float sm[];
    int tid = threadIdx.x;
    int bm = blockIdx.x * 128;
    uint32_t sbase = (uint32_t)__cvta_generic_to_shared(sm);
    uint32_t aB[2]  = {sbase, sbase + (uint32_t)H1_A_WORDS * 4};
    uint32_t bhB[2] = {sbase + (uint32_t)(2 * H1_A_WORDS) * 4,
                       sbase + (uint32_t)(2 * H1_A_WORDS + H1_B_WORDS) * 4};
    uint32_t blB[2] = {sbase + (uint32_t)(2 * H1_A_WORDS + 2 * H1_B_WORDS) * 4,
                       sbase + (uint32_t)(2 * H1_A_WORDS + 3 * H1_B_WORDS) * 4};
    const float* Ap[2] = {sm, sm + H1_A_WORDS};
    const uint32_t* Bhp[2] = {(const uint32_t*)(sm + 2 * H1_A_WORDS),
                              (const uint32_t*)(sm + 2 * H1_A_WORDS + H1_B_WORDS)};
    const uint32_t* Blp[2] = {(const uint32_t*)(sm + 2 * H1_A_WORDS + 2 * H1_B_WORDS),
                              (const uint32_t*)(sm + 2 * H1_A_WORDS + 3 * H1_B_WORDS)};

    int lane = tid & 31, wid = tid >> 5;
    int wm = (wid & 3) * 32, wn = (wid >> 2) * 64;
    int l4 = lane >> 2, lq = lane & 3;
    float acc[2][8][4];
#pragma unroll
    for (int mt = 0; mt < 2; mt++)
#pragma unroll
        for (int nt = 0; nt < 8; nt++)
#pragma unroll
            for (int q = 0; q < 4; q++) acc[mt][nt][q] = 0.f;

    h1_stage(aB[0], bhB[0], blB[0], 0, bm, tid);
    CP_COMMIT;

    for (int it = 0; it < NIT; it++) {
        int cur = it & 1;
        CP_WAIT0;
        __syncthreads();
        if (it + 1 < NIT) {
            h1_stage(aB[1 - cur], bhB[1 - cur], blB[1 - cur], (it + 1) * 32, bm, tid);
            CP_COMMIT;
        }
        const float* Af = Ap[cur];
        const uint32_t* Bhf = Bhp[cur];
        const uint32_t* Blf = Blp[cur];
#pragma unroll
        for (int ks = 0; ks < 4; ks++) {
            int k0 = ks * 8;
            uint32_t ah[2][4], al[2][4];
#pragma unroll
            for (int mt = 0; mt < 2; mt++) {
                int r = wm + mt * 16 + l4;
                tfsplit(Af[r * SA2 + k0 + lq],           ah[mt][0], al[mt][0]);
                tfsplit(Af[(r + 8) * SA2 + k0 + lq],     ah[mt][1], al[mt][1]);
                tfsplit(Af[r * SA2 + k0 + lq + 4],       ah[mt][2], al[mt][2]);
                tfsplit(Af[(r + 8) * SA2 + k0 + lq + 4], ah[mt][3], al[mt][3]);
            }
#pragma unroll
            for (int nt = 0; nt < 8; nt++) {
                int cb = wn + nt * 8 + l4;
                uint32_t b0h = Bhf[(k0 + lq) * SB2 + cb];
                uint32_t b1h = Bhf[(k0 + lq + 4) * SB2 + cb];
                uint32_t b0l = Blf[(k0 + lq) * SB2 + cb];
                uint32_t b1l = Blf[(k0 + lq + 4) * SB2 + cb];
#pragma unroll
                for (int mt = 0; mt < 2; mt++) {
                    mma8(acc[mt][nt], ah[mt], b0h, b1h);
                    mma8(acc[mt][nt], al[mt], b0h, b1h);
                    mma8(acc[mt][nt], ah[mt], b0l, b1l);
                }
            }
        }
        __syncthreads();
    }

#pragma unroll
    for (int mt = 0; mt < 2; mt++)
#pragma unroll
        for (int nt = 0; nt < 8; nt++) {
            int r = bm + wm + mt * 16 + l4;
            int c = wn + nt * 8 + 2 * lq;
            float2 bb = *(const float2*)(b1 + c);
            if (r < N_TX)
                *(float2*)&g_h1[(size_t)r * D + c] =
                    make_float2(fmaxf(acc[mt][nt][0] + bb.x, 0.f),
                                fmaxf(acc[mt][nt][1] + bb.y, 0.f));
            if (r + 8 < N_TX)
                *(float2*)&g_h1[(size_t)(r + 8) * D + c] =
                    make_float2(fmaxf(acc[mt][nt][2] + bb.x, 0.f),
                                fmaxf(acc[mt][nt][3] + bb.y, 0.f));
        }
}

// ================= fused classifier layers 2+3 =================
__global__ void k_h23(const float* __restrict__ w2, const float* __restrict__ b2,
                      const float* __restrict__ w3, const float* __restrict__ b3,
                      float* __restrict__ out) {
    __shared__ float Ws[128 * 64];
    __shared__ float w3s[64];
    int tid = threadIdx.x;
#pragma unroll
    for (int i = 0; i < 8; i++)
        ((float4*)Ws)[tid + i * 256] = ((const float4*)w2)[tid + i * 256];
    if (tid < 64) w3s[tid] = w3[tid];
    __syncthreads();
    int lane = tid & 31, w = tid >> 5;
    for (int rr = 0; rr < 4; rr++) {
        int r = blockIdx.x * 32 + rr * 8 + w;
        if (r >= N_TX) return;
        float4 x = ((const float4*)(g_h1 + (size_t)r * D))[lane];
        float xa[4] = {x.x, x.y, x.z, x.w};
        float a0 = 0.f, a1 = 0.f;
#pragma unroll
        for (int k = 0; k < 128; k++) {
            float xk = __shfl_sync(0xffffffffu, xa[k & 3], k >> 2);
            float2 wv = *(const float2*)&Ws[k * 64 + lane * 2];
            a0 += xk * wv.x;
            a1 += xk * wv.y;
        }
        float2 bb = *(const float2*)&b2[lane * 2];
        float h0 = fmaxf(a0 + bb.x, 0.f);
        float h1v = fmaxf(a1 + bb.y, 0.f);
        float v = h0 * w3s[lane * 2] + h1v * w3s[lane * 2 + 1];
#pragma unroll
        for (int off = 16; off; off >>= 1) v += __shfl_xor_sync(0xffffffffu, v, off);
        if (lane == 0) out[r] = v + b3[0];
    }
}

// ================= launcher =================
extern "C" void kernel_launch(void* const* d_in, const int* in_sizes, int n_in,
                              void* d_out, int out_size) {
    const float* tx_x      = (const float*)d_in[0];
    const float* emb       = (const float*)d_in[1];
    const float* lin_w     = (const float*)d_in[2];
    const float* att_src   = (const float*)d_in[3];
    const float* att_dst   = (const float*)d_in[4];
    const float* conv_bias = (const float*)d_in[5];
    const float* ln_gamma  = (const float*)d_in[6];
    const float* ln_beta   = (const float*)d_in[7];
    const float* w1        = (const float*)d_in[8];
    const float* b1        = (const float*)d_in[9];
    const float* w2        = (const float*)d_in[10];
    const float* b2        = (const float*)d_in[11];
    const float* w3        = (const float*)d_in[12];
    const float* b3        = (const float*)d_in[13];
    const int* entity_idx  = (const int*)d_in[14];
    const int* edge_src    = (const int*)d_in[15];
    const int* edge_dst    = (const int*)d_in[16];
    float* out = (float*)d_out;

    cudaFuncSetAttribute(k_gemm1, cudaFuncAttributeMaxDynamicSharedMemorySize,
                         (128 * SA1 + 2 * 128 * SB1) * 4);
    cudaFuncSetAttribute(k_h1, cudaFuncAttributeMaxDynamicSharedMemorySize,
                         H1_SMEM_W * 4);

    // ---- weight splits (once per launch; deterministic) ----
    k_split_w<<<(COMB_STRIDE * 128 + 255) / 256, 256>>>(lin_w, w1);

    // ---- CSR build ----
    k_zero_cnt<<<(T * N_ENT + 255) / 256, 256>>>();
    { dim3 g((E_EDGES + 255) / 256, T); k_hist<<<g, 256>>>(edge_dst); }
    { dim3 g(NBLK_SCAN, T); k_scan1<<<g, SCAN_BLK>>>(); }
    k_scan2<<<T, 32>>>();
    { dim3 g(NBLK_SCAN, T); k_scan3<<<g, SCAN_BLK>>>(); }
    { dim3 g((E_EDGES + 255) / 256, T); k_fill<<<g, 256>>>(edge_src, edge_dst); }

    // ---- tx into combined buffer (independent) ----
    k_copytx<<<(N_TX + 7) / 8, 256>>>(tx_x);

    // ---- batched GAT pipeline ----
    { dim3 g((N_ENT + 127) / 128, T);
      k_gemm1<<<g, 256, (128 * SA1 + 2 * 128 * SB1) * 4>>>(emb, entity_idx, att_src, att_dst); }
    { dim3 g((N_ENT + 7) / 8, T); k_gat<<<g, 256>>>(conv_bias, ln_gamma, ln_beta); }
    { dim3 g((N_TX + 7) / 8, T); k_msg<<<g, 256>>>(); }

    // ---- classifier ----
    k_h1<<<(N_TX + 127) / 128, 256, H1_SMEM_W * 4>>>(b1);
    k_h23<<<(N_TX + 31) / 32, 256>>>(w2, b2, w3, b3, out);
}

// round 11
// speedup vs baseline: 1.3983x; 1.2829x over previous
#include <cuda_runtime.h>
#include <cuda_fp16.h>
#include <math.h>
#include <stdint.h>

#define T 11
#define N_ENT 100000
#define N_TX 100000
#define D 128
#define E_EDGES 500000
#define F_TX 394
#define COMB_K 1802
#define COMB_STRIDE 1824
#define NEG_SLOPE 0.2f
#define LN_EPS 1e-5f

#define SCAN_BLK 1024
#define NBLK_SCAN ((N_ENT + SCAN_BLK - 1) / SCAN_BLK)   /* 98 */

// ---------------- scratch (device globals; no allocs allowed) ----------------
__device__ __half g_xw[(size_t)T * N_ENT * D];   // fp16 to halve gather bytes
__device__ float g_as[T * N_ENT];
__device__ float g_ad[T * N_ENT];
__device__ __half g_h[(size_t)T * N_ENT * D];    // fp16
__device__ float g_comb[(size_t)N_TX * COMB_STRIDE];   // [msgs 1408 | tx 394 | pad 22]
__device__ float g_h1[(size_t)N_TX * D];

// pre-split fp16 weights in half2 k-pair layout: [k/2][n], pair = (k, k+1) for col n
__device__ uint32_t g_lwh2[64 * 128], g_lwl2[64 * 128];
__device__ uint32_t g_w1h2[(COMB_STRIDE / 2) * 128], g_w1l2[(COMB_STRIDE / 2) * 128];

__device__ int g_cnt[T * N_ENT];
__device__ int g_off[T * N_ENT];
__device__ int g_cur[T * N_ENT];
__device__ int g_csr[(size_t)T * E_EDGES];
__device__ int g_blksum[T * NBLK_SCAN];

// ---------------- helpers ----------------
__device__ __forceinline__ float leaky(float e) { return (e > 0.f) ? e : e * NEG_SLOPE; }

#define FMA4(ACC, S, B) \
    (ACC).x += (S) * (B).x; (ACC).y += (S) * (B).y; \
    (ACC).z += (S) * (B).z; (ACC).w += (S) * (B).w;

__device__ __forceinline__ float4 ld_half4(const __half* row, int lane) {
    uint2 p = ((const uint2*)row)[lane];
    float2 lo = __half22float2(*(__half2*)&p.x);
    float2 hi = __half22float2(*(__half2*)&p.y);
    return make_float4(lo.x, lo.y, hi.x, hi.y);
}
__device__ __forceinline__ void st_half4(__half* row, int lane, float4 v) {
    __half2 h0 = __floats2half2_rn(v.x, v.y);
    __half2 h1 = __floats2half2_rn(v.z, v.w);
    uint2 p;
    p.x = *(uint32_t*)&h0;
    p.y = *(uint32_t*)&h1;
    ((uint2*)row)[lane] = p;
}

__device__ __forceinline__ void cp16(uint32_t s, const void* g) {
    asm volatile("cp.async.cg.shared.global [%0], [%1], 16;" :: "r"(s), "l"(g));
}
#define CP_COMMIT asm volatile("cp.async.commit_group;")
#define CP_WAIT0  asm volatile("cp.async.wait_group 0;")

// fp16 m16n8k16 mma, fp32 accumulate
__device__ __forceinline__ void mma16(float* c, const uint32_t* a, uint32_t b0, uint32_t b1) {
    asm volatile(
        "mma.sync.aligned.m16n8k16.row.col.f32.f16.f16.f32 "
        "{%0,%1,%2,%3}, {%4,%5,%6,%7}, {%8,%9}, {%0,%1,%2,%3};"
        : "+f"(c[0]), "+f"(c[1]), "+f"(c[2]), "+f"(c[3])
        : "r"(a[0]), "r"(a[1]), "r"(a[2]), "r"(a[3]), "r"(b0), "r"(b1));
}

// split a float pair into hi/lo half2
__device__ __forceinline__ void h2split(float x, float y, uint32_t& hi, uint32_t& lo) {
    __half2 h = __floats2half2_rn(x, y);
    float2 hf = __half22float2(h);
    __half2 l = __floats2half2_rn(x - hf.x, y - hf.y);
    hi = *(uint32_t*)&h;
    lo = *(uint32_t*)&l;
}

// ================= weight splitting (once) =================
__global__ void k_split_w(const float* __restrict__ W, const float* __restrict__ w1) {
    int i = blockIdx.x * blockDim.x + threadIdx.x;
    if (i < 64 * 128) {
        int p = i >> 7, c = i & 127;
        uint32_t h, l;
        h2split(W[(2 * p) * 128 + c], W[(2 * p + 1) * 128 + c], h, l);
        g_lwh2[i] = h; g_lwl2[i] = l;
    }
    if (i < (COMB_STRIDE / 2) * 128) {
        int p = i >> 7, c = i & 127;
        int ck0 = 2 * p, ck1 = 2 * p + 1;
        float v0 = 0.f, v1 = 0.f;
        if (ck0 < 1408)          v0 = w1[(size_t)(394 + ck0) * 128 + c];
        else if (ck0 < COMB_K)   v0 = w1[(size_t)(ck0 - 1408) * 128 + c];
        if (ck1 < 1408)          v1 = w1[(size_t)(394 + ck1) * 128 + c];
        else if (ck1 < COMB_K)   v1 = w1[(size_t)(ck1 - 1408) * 128 + c];
        uint32_t h, l;
        h2split(v0, v1, h, l);
        g_w1h2[i] = h; g_w1l2[i] = l;
    }
}

// ================= CSR build =================
__global__ void k_zero_cnt() {
    int i = blockIdx.x * blockDim.x + threadIdx.x;
    if (i < T * N_ENT) g_cnt[i] = 0;
}
__global__ void k_hist(const int* __restrict__ dst) {
    int t = blockIdx.y;
    int i = blockIdx.x * blockDim.x + threadIdx.x;
    if (i < E_EDGES) atomicAdd(&g_cnt[t * N_ENT + dst[(size_t)t * E_EDGES + i]], 1);
}
__global__ void k_scan1() {
    __shared__ int s[SCAN_BLK];
    int t = blockIdx.y, tid = threadIdx.x;
    int idx = blockIdx.x * SCAN_BLK + tid;
    int v = (idx < N_ENT) ? g_cnt[t * N_ENT + idx] : 0;
    s[tid] = v;
    __syncthreads();
#pragma unroll
    for (int off = 1; off < SCAN_BLK; off <<= 1) {
        int y = (tid >= off) ? s[tid - off] : 0;
        __syncthreads();
        s[tid] += y;
        __syncthreads();
    }
    if (idx < N_ENT) g_off[t * N_ENT + idx] = s[tid] - v;
    if (tid == SCAN_BLK - 1) g_blksum[t * NBLK_SCAN + blockIdx.x] = s[tid];
}
__global__ void k_scan2() {
    int t = blockIdx.x;
    if (threadIdx.x == 0) {
        int run = 0;
        for (int b = 0; b < NBLK_SCAN; b++) {
            int v = g_blksum[t * NBLK_SCAN + b];
            g_blksum[t * NBLK_SCAN + b] = run;
            run += v;
        }
    }
}
__global__ void k_scan3() {
    int t = blockIdx.y;
    int idx = blockIdx.x * SCAN_BLK + threadIdx.x;
    if (idx < N_ENT) {
        int v = g_off[t * N_ENT + idx] + g_blksum[t * NBLK_SCAN + blockIdx.x];
        g_off[t * N_ENT + idx] = v;
        g_cur[t * N_ENT + idx] = v;
    }
}
__global__ void k_fill(const int* __restrict__ src, const int* __restrict__ dst) {
    int t = blockIdx.y;
    int i = blockIdx.x * blockDim.x + threadIdx.x;
    if (i < E_EDGES) {
        int d = dst[(size_t)t * E_EDGES + i];
        int pos = atomicAdd(&g_cur[t * N_ENT + d], 1);
        g_csr[(size_t)t * E_EDGES + pos] = src[(size_t)t * E_EDGES + i];
    }
}

// ================= copy tx into combined buffer =================
__global__ void k_copytx(const float* __restrict__ tx) {
    int r = blockIdx.x * 8 + (threadIdx.x >> 5);
    if (r >= N_TX) return;
    int lane = threadIdx.x & 31;
    float* drow = g_comb + (size_t)r * COMB_STRIDE + 1408;
    const float* srow = tx + (size_t)r * F_TX;
    for (int c = lane; c < F_TX; c += 32) drow[c] = srow[c];
    int p = F_TX + lane;
    if (p < COMB_STRIDE - 1408) drow[p] = 0.f;
}

// ================= GEMM1 (3x fp16-split mma): xw = emb[idx] @ W ; a_s, a_d =================
#define SA1 132
#define SBH 136   /* B smem stride in half2 units */
__global__ __launch_bounds__(256, 1) void k_gemm1(
    const float* __restrict__ emb, const int* __restrict__ eidx,
    const float* __restrict__ att_s, const float* __restrict__ att_d) {
    extern __shared__ float sm[];
    float* As = sm;                                       // [128][132] floats
    uint32_t* Bh2 = (uint32_t*)(sm + 128 * SA1);          // [64][136] half2
    uint32_t* Bl2 = Bh2 + 64 * SBH;
    int t = blockIdx.y;
    const float* embt = emb + (size_t)t * N_ENT * D;
    const int* idxt = eidx + (size_t)t * N_ENT;
    int tid = threadIdx.x;
    int bm = blockIdx.x * 128;
    uint32_t sbase = (uint32_t)__cvta_generic_to_shared(sm);
    uint32_t bhbase = sbase + (uint32_t)(128 * SA1) * 4;
    uint32_t blbase = bhbase + (uint32_t)(64 * SBH) * 4;

#pragma unroll
    for (int i = 0; i < 8; i++) {       // stage Bh2/Bl2: 64 rows x 32 chunks (16B = 4 u32)
        int l = tid + i * 256;
        int row = l >> 5, c8 = l & 31;
        cp16(bhbase + (uint32_t)(row * SBH + c8 * 4) * 4, g_lwh2 + row * 128 + c8 * 4);
        cp16(blbase + (uint32_t)(row * SBH + c8 * 4) * 4, g_lwl2 + row * 128 + c8 * 4);
    }
#pragma unroll
    for (int i = 0; i < 16; i++) {      // stage A (gathered rows)
        int l = tid + i * 256;
        int row = l >> 5, c4 = l & 31;
        int rg = bm + row;
        int srcr = (rg < N_ENT) ? idxt[rg] : 0;
        cp16(sbase + (uint32_t)(row * SA1 + 4 * c4) * 4, embt + (size_t)srcr * D + 4 * c4);
    }
    CP_COMMIT; CP_WAIT0;
    __syncthreads();

    int lane = tid & 31, wid = tid >> 5;
    int wm = (wid & 3) * 32, wn = (wid >> 2) * 64;
    int l4 = lane >> 2, lq = lane & 3;
    float acc[2][8][4];
#pragma unroll
    for (int mt = 0; mt < 2; mt++)
#pragma unroll
        for (int nt = 0; nt < 8; nt++)
#pragma unroll
            for (int q = 0; q < 4; q++) acc[mt][nt][q] = 0.f;

    for (int k0 = 0; k0 < 128; k0 += 16) {
        uint32_t ah[2][4], al[2][4];
#pragma unroll
        for (int mt = 0; mt < 2; mt++) {
            int r = wm + mt * 16 + l4;
            float2 x0 = *(const float2*)&As[r * SA1 + k0 + 2 * lq];
            float2 x1 = *(const float2*)&As[(r + 8) * SA1 + k0 + 2 * lq];
            float2 x2 = *(const float2*)&As[r * SA1 + k0 + 8 + 2 * lq];
            float2 x3 = *(const float2*)&As[(r + 8) * SA1 + k0 + 8 + 2 * lq];
            h2split(x0.x, x0.y, ah[mt][0], al[mt][0]);
            h2split(x1.x, x1.y, ah[mt][1], al[mt][1]);
            h2split(x2.x, x2.y, ah[mt][2], al[mt][2]);
            h2split(x3.x, x3.y, ah[mt][3], al[mt][3]);
        }
        int kp = k0 >> 1;
#pragma unroll
        for (int nt = 0; nt < 8; nt++) {
            int cb = wn + nt * 8 + l4;
            uint32_t b0h = Bh2[(kp + lq) * SBH + cb];
            uint32_t b1h = Bh2[(kp + 4 + lq) * SBH + cb];
            uint32_t b0l = Bl2[(kp + lq) * SBH + cb];
            uint32_t b1l = Bl2[(kp + 4 + lq) * SBH + cb];
#pragma unroll
            for (int mt = 0; mt < 2; mt++) {
                mma16(acc[mt][nt], ah[mt], b0h, b1h);
                mma16(acc[mt][nt], al[mt], b0h, b1h);
                mma16(acc[mt][nt], ah[mt], b0l, b1l);
            }
        }
    }
    __syncthreads();
    float* Cs = As;   // reuse
#pragma unroll
    for (int mt = 0; mt < 2; mt++)
#pragma unroll
        for (int nt = 0; nt < 8; nt++) {
            int r = wm + mt * 16 + l4;
            int c = wn + nt * 8 + 2 * lq;
            *(float2*)&Cs[r * SA1 + c] = make_float2(acc[mt][nt][0], acc[mt][nt][1]);
            *(float2*)&Cs[(r + 8) * SA1 + c] = make_float2(acc[mt][nt][2], acc[mt][nt][3]);
        }
    __syncthreads();

    float4 aS = ((const float4*)att_s)[lane];
    float4 aD = ((const float4*)att_d)[lane];
    for (int i = 0; i < 16; i++) {
        int row = wid * 16 + i;
        int rg = bm + row;
        if (rg >= N_ENT) break;
        float4 v = *(float4*)&Cs[row * SA1 + 4 * lane];
        st_half4(g_xw + ((size_t)t * N_ENT + rg) * D, lane, v);
        float s = v.x * aS.x + v.y * aS.y + v.z * aS.z + v.w * aS.w;
        float d = v.x * aD.x + v.y * aD.y + v.z * aD.z + v.w * aD.w;
#pragma unroll
        for (int off = 16; off; off >>= 1) {
            s += __shfl_xor_sync(0xffffffffu, s, off);
            d += __shfl_xor_sync(0xffffffffu, d, off);
        }
        if (lane == 0) { g_as[t * N_ENT + rg] = s; g_ad[t * N_ENT + rg] = d; }
    }
}

// ================= fused GAT: single-pass softmax+aggregate + bias + LN =================
__global__ void k_gat(const float* __restrict__ conv_bias,
                      const float* __restrict__ gamma_all, const float* __restrict__ beta_all) {
    int t = blockIdx.y;
    int dn = blockIdx.x * 8 + (threadIdx.x >> 5);
    if (dn >= N_ENT) return;
    int lane = threadIdx.x & 31;
    const float* asv = g_as + t * N_ENT;
    float ad = g_ad[t * N_ENT + dn];
    int off0 = g_off[t * N_ENT + dn];
    int off1 = (dn + 1 < N_ENT) ? g_off[t * N_ENT + dn + 1] : E_EDGES;
    const int* csr = g_csr + (size_t)t * E_EDGES;
    const __half* xw = g_xw + (size_t)t * N_ENT * D;

    float ex_self = __expf(leaky(asv[dn] + ad));
    float wsum = ex_self;
    float4 vs = ld_half4(xw + (size_t)dn * D, lane);
    float4 acc = make_float4(ex_self * vs.x, ex_self * vs.y, ex_self * vs.z, ex_self * vs.w);

    for (int j = off0; j < off1; j++) {
        int s = csr[j];
        float e = __expf(leaky(asv[s] + ad));
        float4 v = ld_half4(xw + (size_t)s * D, lane);
        FMA4(acc, e, v);
        wsum += e;
    }
    float inv = 1.f / (wsum + 1e-16f);
    acc.x *= inv; acc.y *= inv; acc.z *= inv; acc.w *= inv;

    float4 cb = ((const float4*)conv_bias)[lane];
    acc.x += cb.x; acc.y += cb.y; acc.z += cb.z; acc.w += cb.w;
    float sum = acc.x + acc.y + acc.z + acc.w;
#pragma unroll
    for (int off = 16; off; off >>= 1) sum += __shfl_xor_sync(0xffffffffu, sum, off);
    float mu = sum * (1.f / D);
    float4 dd = make_float4(acc.x - mu, acc.y - mu, acc.z - mu, acc.w - mu);
    float sq = dd.x * dd.x + dd.y * dd.y + dd.z * dd.z + dd.w * dd.w;
#pragma unroll
    for (int off = 16; off; off >>= 1) sq += __shfl_xor_sync(0xffffffffu, sq, off);
    float invs = rsqrtf(sq * (1.f / D) + LN_EPS);
    float4 gm = ((const float4*)(gamma_all + t * D))[lane];
    float4 bt = ((const float4*)(beta_all + t * D))[lane];
    float4 h;
    h.x = dd.x * invs * gm.x + bt.x;
    h.y = dd.y * invs * gm.y + bt.y;
    h.z = dd.z * invs * gm.z + bt.z;
    h.w = dd.w * invs * gm.w + bt.w;
    st_half4(g_h + ((size_t)t * N_ENT + dn) * D, lane, h);
}

// ================= msg gather into combined buffer =================
__global__ void k_msg() {
    int t = blockIdx.y;
    int dn = blockIdx.x * 8 + (threadIdx.x >> 5);
    if (dn >= N_TX) return;
    int lane = threadIdx.x & 31;
    int off0 = g_off[t * N_ENT + dn];
    int off1 = (dn + 1 < N_ENT) ? g_off[t * N_ENT + dn + 1] : E_EDGES;
    const int* csr = g_csr + (size_t)t * E_EDGES;
    const __half* h = g_h + (size_t)t * N_ENT * D;
    float4 acc = make_float4(0.f, 0.f, 0.f, 0.f);
    for (int j = off0; j < off1; j++) {
        float4 v = ld_half4(h + (size_t)csr[j] * D, lane);
        acc.x += v.x; acc.y += v.y; acc.z += v.z; acc.w += v.w;
    }
    ((float4*)(g_comb + (size_t)dn * COMB_STRIDE + t * D))[lane] = acc;
}

// ================= classifier layer 1 (3x fp16-split mma, double-buffered) =================
#define SA2 36
#define NIT 57   /* 1824 / 32 */
#define H1_A_WORDS   (128 * SA2)
#define H1_B_WORDS   (16 * SBH)          /* 16 k-pairs x 136 half2 per plane */
#define H1_SMEM_W    (2 * H1_A_WORDS + 4 * H1_B_WORDS)

__device__ __forceinline__ void h1_stage(uint32_t abase, uint32_t bhbase, uint32_t blbase,
                                         int kc, int bm, int tid) {
#pragma unroll
    for (int i = 0; i < 4; i++) {       // A: 128 rows x 8 float4 (32 floats)
        int l = tid + i * 256;
        int row = l >> 3, c4 = l & 7;
        int rg = bm + row;
        if (rg >= N_TX) rg = 0;
        cp16(abase + (uint32_t)(row * SA2 + 4 * c4) * 4,
             g_comb + (size_t)rg * COMB_STRIDE + kc + 4 * c4);
    }
    int kcp = kc >> 1;                  // first k-pair of this tile
#pragma unroll
    for (int i = 0; i < 2; i++) {       // Bh2/Bl2: 16 rows x 32 chunks (16B = 4 u32)
        int l = tid + i * 256;
        int kk = l >> 5, c8 = l & 31;
        cp16(bhbase + (uint32_t)(kk * SBH + c8 * 4) * 4,
             g_w1h2 + (size_t)(kcp + kk) * 128 + c8 * 4);
        cp16(blbase + (uint32_t)(kk * SBH + c8 * 4) * 4,
             g_w1l2 + (size_t)(kcp + kk) * 128 + c8 * 4);
    }
}

__global__ __launch_bounds__(256, 2) void k_h1(const float* __restrict__ b1) {
    extern __shared__ float sm[];
    int tid = threadIdx.x;
    int bm = blockIdx.x * 128;
    uint32_t sbase = (uint32_t)__cvta_generic_to_shared(sm);
    uint32_t aB[2]  = {sbase, sbase + (uint32_t)H1_A_WORDS * 4};
    uint32_t bhB[2] = {sbase + (uint32_t)(2 * H1_A_WORDS) * 4,
                       sbase + (uint32_t)(2 * H1_A_WORDS + H1_B_WORDS) * 4};
    uint32_t blB[2] = {sbase + (uint32_t)(2 * H1_A_WORDS + 2 * H1_B_WORDS) * 4,
                       sbase + (uint32_t)(2 * H1_A_WORDS + 3 * H1_B_WORDS) * 4};
    const float* Ap[2] = {sm, sm + H1_A_WORDS};
    const uint32_t* Bhp[2] = {(const uint32_t*)(sm + 2 * H1_A_WORDS),
                              (const uint32_t*)(sm + 2 * H1_A_WORDS + H1_B_WORDS)};
    const uint32_t* Blp[2] = {(const uint32_t*)(sm + 2 * H1_A_WORDS + 2 * H1_B_WORDS),
                              (const uint32_t*)(sm + 2 * H1_A_WORDS + 3 * H1_B_WORDS)};

    int lane = tid & 31, wid = tid >> 5;
    int wm = (wid & 3) * 32, wn = (wid >> 2) * 64;
    int l4 = lane >> 2, lq = lane & 3;
    float acc[2][8][4];
#pragma unroll
    for (int mt = 0; mt < 2; mt++)
#pragma unroll
        for (int nt = 0; nt < 8; nt++)
#pragma unroll
            for (int q = 0; q < 4; q++) acc[mt][nt][q] = 0.f;

    h1_stage(aB[0], bhB[0], blB[0], 0, bm, tid);
    CP_COMMIT;

    for (int it = 0; it < NIT; it++) {
        int cur = it & 1;
        CP_WAIT0;
        __syncthreads();
        if (it + 1 < NIT) {
            h1_stage(aB[1 - cur], bhB[1 - cur], blB[1 - cur], (it + 1) * 32, bm, tid);
            CP_COMMIT;
        }
        const float* Af = Ap[cur];
        const uint32_t* Bhf = Bhp[cur];
        const uint32_t* Blf = Blp[cur];
#pragma unroll
        for (int ks = 0; ks < 2; ks++) {
            int k0 = ks * 16;
            uint32_t ah[2][4], al[2][4];
#pragma unroll
            for (int mt = 0; mt < 2; mt++) {
                int r = wm + mt * 16 + l4;
                float2 x0 = *(const float2*)&Af[r * SA2 + k0 + 2 * lq];
                float2 x1 = *(const float2*)&Af[(r + 8) * SA2 + k0 + 2 * lq];
                float2 x2 = *(const float2*)&Af[r * SA2 + k0 + 8 + 2 * lq];
                float2 x3 = *(const float2*)&Af[(r + 8) * SA2 + k0 + 8 + 2 * lq];
                h2split(x0.x, x0.y, ah[mt][0], al[mt][0]);
                h2split(x1.x, x1.y, ah[mt][1], al[mt][1]);
                h2split(x2.x, x2.y, ah[mt][2], al[mt][2]);
                h2split(x3.x, x3.y, ah[mt][3], al[mt][3]);
            }
            int kp = k0 >> 1;
#pragma unroll
            for (int nt = 0; nt < 8; nt++) {
                int cb = wn + nt * 8 + l4;
                uint32_t b0h = Bhf[(kp + lq) * SBH + cb];
                uint32_t b1h = Bhf[(kp + 4 + lq) * SBH + cb];
                uint32_t b0l = Blf[(kp + lq) * SBH + cb];
                uint32_t b1l = Blf[(kp + 4 + lq) * SBH + cb];
#pragma unroll
                for (int mt = 0; mt < 2; mt++) {
                    mma16(acc[mt][nt], ah[mt], b0h, b1h);
                    mma16(acc[mt][nt], al[mt], b0h, b1h);
                    mma16(acc[mt][nt], ah[mt], b0l, b1l);
                }
            }
        }
        __syncthreads();
    }

#pragma unroll
    for (int mt = 0; mt < 2; mt++)
#pragma unroll
        for (int nt = 0; nt < 8; nt++) {
            int r = bm + wm + mt * 16 + l4;
            int c = wn + nt * 8 + 2 * lq;
            float2 bb = *(const float2*)(b1 + c);
            if (r < N_TX)
                *(float2*)&g_h1[(size_t)r * D + c] =
                    make_float2(fmaxf(acc[mt][nt][0] + bb.x, 0.f),
                                fmaxf(acc[mt][nt][1] + bb.y, 0.f));
            if (r + 8 < N_TX)
                *(float2*)&g_h1[(size_t)(r + 8) * D + c] =
                    make_float2(fmaxf(acc[mt][nt][2] + bb.x, 0.f),
                                fmaxf(acc[mt][nt][3] + bb.y, 0.f));
        }
}

// ================= fused classifier layers 2+3 =================
__global__ void k_h23(const float* __restrict__ w2, const float* __restrict__ b2,
                      const float* __restrict__ w3, const float* __restrict__ b3,
                      float* __restrict__ out) {
    __shared__ float Ws[128 * 64];
    __shared__ float w3s[64];
    int tid = threadIdx.x;
#pragma unroll
    for (int i = 0; i < 8; i++)
        ((float4*)Ws)[tid + i * 256] = ((const float4*)w2)[tid + i * 256];
    if (tid < 64) w3s[tid] = w3[tid];
    __syncthreads();
    int lane = tid & 31, w = tid >> 5;
    for (int rr = 0; rr < 4; rr++) {
        int r = blockIdx.x * 32 + rr * 8 + w;
        if (r >= N_TX) return;
        float4 x = ((const float4*)(g_h1 + (size_t)r * D))[lane];
        float xa[4] = {x.x, x.y, x.z, x.w};
        float a0 = 0.f, a1 = 0.f;
#pragma unroll
        for (int k = 0; k < 128; k++) {
            float xk = __shfl_sync(0xffffffffu, xa[k & 3], k >> 2);
            float2 wv = *(const float2*)&Ws[k * 64 + lane * 2];
            a0 += xk * wv.x;
            a1 += xk * wv.y;
        }
        float2 bb = *(const float2*)&b2[lane * 2];
        float h0 = fmaxf(a0 + bb.x, 0.f);
        float h1v = fmaxf(a1 + bb.y, 0.f);
        float v = h0 * w3s[lane * 2] + h1v * w3s[lane * 2 + 1];
#pragma unroll
        for (int off = 16; off; off >>= 1) v += __shfl_xor_sync(0xffffffffu, v, off);
        if (lane == 0) out[r] = v + b3[0];
    }
}

// ================= launcher =================
extern "C" void kernel_launch(void* const* d_in, const int* in_sizes, int n_in,
                              void* d_out, int out_size) {
    const float* tx_x      = (const float*)d_in[0];
    const float* emb       = (const float*)d_in[1];
    const float* lin_w     = (const float*)d_in[2];
    const float* att_src   = (const float*)d_in[3];
    const float* att_dst   = (const float*)d_in[4];
    const float* conv_bias = (const float*)d_in[5];
    const float* ln_gamma  = (const float*)d_in[6];
    const float* ln_beta   = (const float*)d_in[7];
    const float* w1        = (const float*)d_in[8];
    const float* b1        = (const float*)d_in[9];
    const float* w2        = (const float*)d_in[10];
    const float* b2        = (const float*)d_in[11];
    const float* w3        = (const float*)d_in[12];
    const float* b3        = (const float*)d_in[13];
    const int* entity_idx  = (const int*)d_in[14];
    const int* edge_src    = (const int*)d_in[15];
    const int* edge_dst    = (const int*)d_in[16];
    float* out = (float*)d_out;

    cudaFuncSetAttribute(k_gemm1, cudaFuncAttributeMaxDynamicSharedMemorySize,
                         (128 * SA1 + 2 * 64 * SBH) * 4);
    cudaFuncSetAttribute(k_h1, cudaFuncAttributeMaxDynamicSharedMemorySize,
                         H1_SMEM_W * 4);

    // ---- weight splits (once per launch; deterministic) ----
    k_split_w<<<((COMB_STRIDE / 2) * 128 + 255) / 256, 256>>>(lin_w, w1);

    // ---- CSR build ----
    k_zero_cnt<<<(T * N_ENT + 255) / 256, 256>>>();
    { dim3 g((E_EDGES + 255) / 256, T); k_hist<<<g, 256>>>(edge_dst); }
    { dim3 g(NBLK_SCAN, T); k_scan1<<<g, SCAN_BLK>>>(); }
    k_scan2<<<T, 32>>>();
    { dim3 g(NBLK_SCAN, T); k_scan3<<<g, SCAN_BLK>>>(); }
    { dim3 g((E_EDGES + 255) / 256, T); k_fill<<<g, 256>>>(edge_src, edge_dst); }

    // ---- tx into combined buffer (independent) ----
    k_copytx<<<(N_TX + 7) / 8, 256>>>(tx_x);

    // ---- batched GAT pipeline ----
    { dim3 g((N_ENT + 127) / 128, T);
      k_gemm1<<<g, 256, (128 * SA1 + 2 * 64 * SBH) * 4>>>(emb, entity_idx, att_src, att_dst); }
    { dim3 g((N_ENT + 7) / 8, T); k_gat<<<g, 256>>>(conv_bias, ln_gamma, ln_beta); }
    { dim3 g((N_TX + 7) / 8, T); k_msg<<<g, 256>>>(); }

    // ---- classifier ----
    k_h1<<<(N_TX + 127) / 128, 256, H1_SMEM_W * 4>>>(b1);
    k_h23<<<(N_TX + 31) / 32, 256>>>(w2, b2, w3, b3, out);
}

// round 13
// speedup vs baseline: 1.5272x; 1.0922x over previous
#include <cuda_runtime.h>
#include <cuda_fp16.h>
#include <math.h>
#include <stdint.h>

#define T 11
#define N_ENT 100000
#define N_TX 100000
#define D 128
#define E_EDGES 500000
#define F_TX 394
#define COMB_K 1802
#define COMB_STRIDE 1824
#define NEG_SLOPE 0.2f
#define LN_EPS 1e-5f

#define SCAN_BLK 1024
#define NBLK_SCAN ((N_ENT + SCAN_BLK - 1) / SCAN_BLK)   /* 98 */

// ---------------- scratch (device globals; no allocs allowed) ----------------
__device__ __half g_xw[(size_t)T * N_ENT * D];   // fp16 to halve gather bytes
__device__ float g_as[T * N_ENT];
__device__ float g_ad[T * N_ENT];
__device__ __half g_h[(size_t)T * N_ENT * D];    // fp16
__device__ __half g_comb[(size_t)N_TX * COMB_STRIDE];  // fp16 [msgs 1408 | tx 394 | pad 22]
__device__ float g_h1[(size_t)N_TX * D];

// pre-split fp16 weights in half2 k-pair layout: [k/2][n], pair = (k, k+1) for col n
__device__ uint32_t g_lwh2[64 * 128], g_lwl2[64 * 128];
__device__ uint32_t g_w1h2[(COMB_STRIDE / 2) * 128], g_w1l2[(COMB_STRIDE / 2) * 128];

__device__ int g_cnt[T * N_ENT];
__device__ int g_off[T * N_ENT];
__device__ int g_cur[T * N_ENT];
__device__ int g_csr[(size_t)T * E_EDGES];
__device__ int g_blksum[T * NBLK_SCAN];

// ---------------- helpers ----------------
__device__ __forceinline__ float leaky(float e) { return (e > 0.f) ? e : e * NEG_SLOPE; }

#define FMA4(ACC, S, B) \
    (ACC).x += (S) * (B).x; (ACC).y += (S) * (B).y; \
    (ACC).z += (S) * (B).z; (ACC).w += (S) * (B).w;

__device__ __forceinline__ float4 ld_half4(const __half* row, int lane) {
    uint2 p = ((const uint2*)row)[lane];
    float2 lo = __half22float2(*(__half2*)&p.x);
    float2 hi = __half22float2(*(__half2*)&p.y);
    return make_float4(lo.x, lo.y, hi.x, hi.y);
}
__device__ __forceinline__ void st_half4(__half* row, int lane, float4 v) {
    __half2 h0 = __floats2half2_rn(v.x, v.y);
    __half2 h1 = __floats2half2_rn(v.z, v.w);
    uint2 p;
    p.x = *(uint32_t*)&h0;
    p.y = *(uint32_t*)&h1;
    ((uint2*)row)[lane] = p;
}

__device__ __forceinline__ void cp16(uint32_t s, const void* g) {
    asm volatile("cp.async.cg.shared.global [%0], [%1], 16;" :: "r"(s), "l"(g));
}
#define CP_COMMIT asm volatile("cp.async.commit_group;")
#define CP_WAIT0  asm volatile("cp.async.wait_group 0;")

// fp16 m16n8k16 mma, fp32 accumulate
__device__ __forceinline__ void mma16(float* c, const uint32_t* a, uint32_t b0, uint32_t b1) {
    asm volatile(
        "mma.sync.aligned.m16n8k16.row.col.f32.f16.f16.f32 "
        "{%0,%1,%2,%3}, {%4,%5,%6,%7}, {%8,%9}, {%0,%1,%2,%3};"
        : "+f"(c[0]), "+f"(c[1]), "+f"(c[2]), "+f"(c[3])
        : "r"(a[0]), "r"(a[1]), "r"(a[2]), "r"(a[3]), "r"(b0), "r"(b1));
}

// split a float pair into hi/lo half2
__device__ __forceinline__ void h2split(float x, float y, uint32_t& hi, uint32_t& lo) {
    __half2 h = __floats2half2_rn(x, y);
    float2 hf = __half22float2(h);
    __half2 l = __floats2half2_rn(x - hf.x, y - hf.y);
    hi = *(uint32_t*)&h;
    lo = *(uint32_t*)&l;
}

// ================= weight splitting (once) =================
__global__ void k_split_w(const float* __restrict__ W, const float* __restrict__ w1) {
    int i = blockIdx.x * blockDim.x + threadIdx.x;
    if (i < 64 * 128) {
        int p = i >> 7, c = i & 127;
        uint32_t h, l;
        h2split(W[(2 * p) * 128 + c], W[(2 * p + 1) * 128 + c], h, l);
        g_lwh2[i] = h; g_lwl2[i] = l;
    }
    if (i < (COMB_STRIDE / 2) * 128) {
        int p = i >> 7, c = i & 127;
        int ck0 = 2 * p, ck1 = 2 * p + 1;
        float v0 = 0.f, v1 = 0.f;
        if (ck0 < 1408)          v0 = w1[(size_t)(394 + ck0) * 128 + c];
        else if (ck0 < COMB_K)   v0 = w1[(size_t)(ck0 - 1408) * 128 + c];
        if (ck1 < 1408)          v1 = w1[(size_t)(394 + ck1) * 128 + c];
        else if (ck1 < COMB_K)   v1 = w1[(size_t)(ck1 - 1408) * 128 + c];
        uint32_t h, l;
        h2split(v0, v1, h, l);
        g_w1h2[i] = h; g_w1l2[i] = l;
    }
}

// ================= CSR build =================
__global__ void k_zero_cnt() {
    int i = blockIdx.x * blockDim.x + threadIdx.x;
    if (i < T * N_ENT) g_cnt[i] = 0;
}
__global__ void k_hist(const int* __restrict__ dst) {
    int t = blockIdx.y;
    int i = blockIdx.x * blockDim.x + threadIdx.x;
    if (i < E_EDGES) atomicAdd(&g_cnt[t * N_ENT + dst[(size_t)t * E_EDGES + i]], 1);
}
__global__ void k_scan1() {
    __shared__ int s[SCAN_BLK];
    int t = blockIdx.y, tid = threadIdx.x;
    int idx = blockIdx.x * SCAN_BLK + tid;
    int v = (idx < N_ENT) ? g_cnt[t * N_ENT + idx] : 0;
    s[tid] = v;
    __syncthreads();
#pragma unroll
    for (int off = 1; off < SCAN_BLK; off <<= 1) {
        int y = (tid >= off) ? s[tid - off] : 0;
        __syncthreads();
        s[tid] += y;
        __syncthreads();
    }
    if (idx < N_ENT) g_off[t * N_ENT + idx] = s[tid] - v;
    if (tid == SCAN_BLK - 1) g_blksum[t * NBLK_SCAN + blockIdx.x] = s[tid];
}
__global__ void k_scan2() {
    int t = blockIdx.x;
    if (threadIdx.x == 0) {
        int run = 0;
        for (int b = 0; b < NBLK_SCAN; b++) {
            int v = g_blksum[t * NBLK_SCAN + b];
            g_blksum[t * NBLK_SCAN + b] = run;
            run += v;
        }
    }
}
__global__ void k_scan3() {
    int t = blockIdx.y;
    int idx = blockIdx.x * SCAN_BLK + threadIdx.x;
    if (idx < N_ENT) {
        int v = g_off[t * N_ENT + idx] + g_blksum[t * NBLK_SCAN + blockIdx.x];
        g_off[t * N_ENT + idx] = v;
        g_cur[t * N_ENT + idx] = v;
    }
}
__global__ void k_fill(const int* __restrict__ src, const int* __restrict__ dst) {
    int t = blockIdx.y;
    int i = blockIdx.x * blockDim.x + threadIdx.x;
    if (i < E_EDGES) {
        int d = dst[(size_t)t * E_EDGES + i];
        int pos = atomicAdd(&g_cur[t * N_ENT + d], 1);
        g_csr[(size_t)t * E_EDGES + pos] = src[(size_t)t * E_EDGES + i];
    }
}

// ================= copy tx into combined buffer (fp16) =================
__global__ void k_copytx(const float* __restrict__ tx) {
    int r = blockIdx.x * 8 + (threadIdx.x >> 5);
    if (r >= N_TX) return;
    int lane = threadIdx.x & 31;
    __half* drow = g_comb + (size_t)r * COMB_STRIDE + 1408;
    const float* srow = tx + (size_t)r * F_TX;
    for (int c = lane; c < F_TX; c += 32) drow[c] = __float2half_rn(srow[c]);
    int p = F_TX + lane;
    if (p < COMB_STRIDE - 1408) drow[p] = __float2half_rn(0.f);
}

// ================= GEMM1 (3x fp16-split mma): xw = emb[idx] @ W ; a_s, a_d =================
#define SA1 132
#define SBH 136   /* B smem stride in half2 units */
__global__ __launch_bounds__(256, 1) void k_gemm1(
    const float* __restrict__ emb, const int* __restrict__ eidx,
    const float* __restrict__ att_s, const float* __restrict__ att_d) {
    extern __shared__ float sm[];
    float* As = sm;                                       // [128][132] floats
    uint32_t* Bh2 = (uint32_t*)(sm + 128 * SA1);          // [64][136] half2
    uint32_t* Bl2 = Bh2 + 64 * SBH;
    int t = blockIdx.y;
    const float* embt = emb + (size_t)t * N_ENT * D;
    const int* idxt = eidx + (size_t)t * N_ENT;
    int tid = threadIdx.x;
    int bm = blockIdx.x * 128;
    uint32_t sbase = (uint32_t)__cvta_generic_to_shared(sm);
    uint32_t bhbase = sbase + (uint32_t)(128 * SA1) * 4;
    uint32_t blbase = bhbase + (uint32_t)(64 * SBH) * 4;

#pragma unroll
    for (int i = 0; i < 8; i++) {       // stage Bh2/Bl2: 64 rows x 32 chunks (16B = 4 u32)
        int l = tid + i * 256;
        int row = l >> 5, c8 = l & 31;
        cp16(bhbase + (uint32_t)(row * SBH + c8 * 4) * 4, g_lwh2 + row * 128 + c8 * 4);
        cp16(blbase + (uint32_t)(row * SBH + c8 * 4) * 4, g_lwl2 + row * 128 + c8 * 4);
    }
#pragma unroll
    for (int i = 0; i < 16; i++) {      // stage A (gathered rows)
        int l = tid + i * 256;
        int row = l >> 5, c4 = l & 31;
        int rg = bm + row;
        int srcr = (rg < N_ENT) ? idxt[rg] : 0;
        cp16(sbase + (uint32_t)(row * SA1 + 4 * c4) * 4, embt + (size_t)srcr * D + 4 * c4);
    }
    CP_COMMIT; CP_WAIT0;
    __syncthreads();

    int lane = tid & 31, wid = tid >> 5;
    int wm = (wid & 3) * 32, wn = (wid >> 2) * 64;
    int l4 = lane >> 2, lq = lane & 3;
    float acc[2][8][4];
#pragma unroll
    for (int mt = 0; mt < 2; mt++)
#pragma unroll
        for (int nt = 0; nt < 8; nt++)
#pragma unroll
            for (int q = 0; q < 4; q++) acc[mt][nt][q] = 0.f;

    for (int k0 = 0; k0 < 128; k0 += 16) {
        uint32_t ah[2][4], al[2][4];
#pragma unroll
        for (int mt = 0; mt < 2; mt++) {
            int r = wm + mt * 16 + l4;
            float2 x0 = *(const float2*)&As[r * SA1 + k0 + 2 * lq];
            float2 x1 = *(const float2*)&As[(r + 8) * SA1 + k0 + 2 * lq];
            float2 x2 = *(const float2*)&As[r * SA1 + k0 + 8 + 2 * lq];
            float2 x3 = *(const float2*)&As[(r + 8) * SA1 + k0 + 8 + 2 * lq];
            h2split(x0.x, x0.y, ah[mt][0], al[mt][0]);
            h2split(x1.x, x1.y, ah[mt][1], al[mt][1]);
            h2split(x2.x, x2.y, ah[mt][2], al[mt][2]);
            h2split(x3.x, x3.y, ah[mt][3], al[mt][3]);
        }
        int kp = k0 >> 1;
#pragma unroll
        for (int nt = 0; nt < 8; nt++) {
            int cb = wn + nt * 8 + l4;
            uint32_t b0h = Bh2[(kp + lq) * SBH + cb];
            uint32_t b1h = Bh2[(kp + 4 + lq) * SBH + cb];
            uint32_t b0l = Bl2[(kp + lq) * SBH + cb];
            uint32_t b1l = Bl2[(kp + 4 + lq) * SBH + cb];
#pragma unroll
            for (int mt = 0; mt < 2; mt++) {
                mma16(acc[mt][nt], ah[mt], b0h, b1h);
                mma16(acc[mt][nt], al[mt], b0h, b1h);
                mma16(acc[mt][nt], ah[mt], b0l, b1l);
            }
        }
    }
    __syncthreads();
    float* Cs = As;   // reuse
#pragma unroll
    for (int mt = 0; mt < 2; mt++)
#pragma unroll
        for (int nt = 0; nt < 8; nt++) {
            int r = wm + mt * 16 + l4;
            int c = wn + nt * 8 + 2 * lq;
            *(float2*)&Cs[r * SA1 + c] = make_float2(acc[mt][nt][0], acc[mt][nt][1]);
            *(float2*)&Cs[(r + 8) * SA1 + c] = make_float2(acc[mt][nt][2], acc[mt][nt][3]);
        }
    __syncthreads();

    float4 aS = ((const float4*)att_s)[lane];
    float4 aD = ((const float4*)att_d)[lane];
    for (int i = 0; i < 16; i++) {
        int row = wid * 16 + i;
        int rg = bm + row;
        if (rg >= N_ENT) break;
        float4 v = *(float4*)&Cs[row * SA1 + 4 * lane];
        st_half4(g_xw + ((size_t)t * N_ENT + rg) * D, lane, v);
        float s = v.x * aS.x + v.y * aS.y + v.z * aS.z + v.w * aS.w;
        float d = v.x * aD.x + v.y * aD.y + v.z * aD.z + v.w * aD.w;
#pragma unroll
        for (int off = 16; off; off >>= 1) {
            s += __shfl_xor_sync(0xffffffffu, s, off);
            d += __shfl_xor_sync(0xffffffffu, d, off);
        }
        if (lane == 0) { g_as[t * N_ENT + rg] = s; g_ad[t * N_ENT + rg] = d; }
    }
}

// ================= fused GAT: single-pass softmax+aggregate + bias + LN =================
__global__ void k_gat(const float* __restrict__ conv_bias,
                      const float* __restrict__ gamma_all, const float* __restrict__ beta_all) {
    int t = blockIdx.y;
    int dn = blockIdx.x * 8 + (threadIdx.x >> 5);
    if (dn >= N_ENT) return;
    int lane = threadIdx.x & 31;
    const float* asv = g_as + t * N_ENT;
    float ad = g_ad[t * N_ENT + dn];
    int off0 = g_off[t * N_ENT + dn];
    int off1 = (dn + 1 < N_ENT) ? g_off[t * N_ENT + dn + 1] : E_EDGES;
    const int* csr = g_csr + (size_t)t * E_EDGES;
    const __half* xw = g_xw + (size_t)t * N_ENT * D;

    float ex_self = __expf(leaky(asv[dn] + ad));
    float wsum = ex_self;
    float4 vs = ld_half4(xw + (size_t)dn * D, lane);
    float4 acc = make_float4(ex_self * vs.x, ex_self * vs.y, ex_self * vs.z, ex_self * vs.w);

    for (int j = off0; j < off1; j++) {
        int s = csr[j];
        float e = __expf(leaky(asv[s] + ad));
        float4 v = ld_half4(xw + (size_t)s * D, lane);
        FMA4(acc, e, v);
        wsum += e;
    }
    float inv = 1.f / (wsum + 1e-16f);
    acc.x *= inv; acc.y *= inv; acc.z *= inv; acc.w *= inv;

    float4 cb = ((const float4*)conv_bias)[lane];
    acc.x += cb.x; acc.y += cb.y; acc.z += cb.z; acc.w += cb.w;
    float sum = acc.x + acc.y + acc.z + acc.w;
#pragma unroll
    for (int off = 16; off; off >>= 1) sum += __shfl_xor_sync(0xffffffffu, sum, off);
    float mu = sum * (1.f / D);
    float4 dd = make_float4(acc.x - mu, acc.y - mu, acc.z - mu, acc.w - mu);
    float sq = dd.x * dd.x + dd.y * dd.y + dd.z * dd.z + dd.w * dd.w;
#pragma unroll
    for (int off = 16; off; off >>= 1) sq += __shfl_xor_sync(0xffffffffu, sq, off);
    float invs = rsqrtf(sq * (1.f / D) + LN_EPS);
    float4 gm = ((const float4*)(gamma_all + t * D))[lane];
    float4 bt = ((const float4*)(beta_all + t * D))[lane];
    float4 h;
    h.x = dd.x * invs * gm.x + bt.x;
    h.y = dd.y * invs * gm.y + bt.y;
    h.z = dd.z * invs * gm.z + bt.z;
    h.w = dd.w * invs * gm.w + bt.w;
    st_half4(g_h + ((size_t)t * N_ENT + dn) * D, lane, h);
}

// ================= msg gather into combined buffer (fp16 out) =================
__global__ void k_msg() {
    int t = blockIdx.y;
    int dn = blockIdx.x * 8 + (threadIdx.x >> 5);
    if (dn >= N_TX) return;
    int lane = threadIdx.x & 31;
    int off0 = g_off[t * N_ENT + dn];
    int off1 = (dn + 1 < N_ENT) ? g_off[t * N_ENT + dn + 1] : E_EDGES;
    const int* csr = g_csr + (size_t)t * E_EDGES;
    const __half* h = g_h + (size_t)t * N_ENT * D;
    float4 acc = make_float4(0.f, 0.f, 0.f, 0.f);
    for (int j = off0; j < off1; j++) {
        float4 v = ld_half4(h + (size_t)csr[j] * D, lane);
        acc.x += v.x; acc.y += v.y; acc.z += v.z; acc.w += v.w;
    }
    st_half4(g_comb + (size_t)dn * COMB_STRIDE + t * D, lane, acc);
}

// ================= classifier layer 1 (A fp16 direct + 2-term B-split mma) =================
#define SA2P 20   /* A smem stride in half2 (u32) units: 16 pairs + 4 pad */
#define NIT 57    /* 1824 / 32 */
#define H1_A_WORDS   (128 * SA2P)        /* 2560 u32 per stage */
#define H1_B_WORDS   (16 * SBH)          /* 2176 u32 per plane */
#define H1_SMEM_W    (2 * H1_A_WORDS + 4 * H1_B_WORDS)   /* 13824 u32 = 55 KB */

__device__ __forceinline__ void h1_stage(uint32_t abase, uint32_t bhbase, uint32_t blbase,
                                         int kc, int bm, int tid) {
#pragma unroll
    for (int i = 0; i < 2; i++) {       // A: 128 rows x 4 chunks (16B = 8 halves)
        int l = tid + i * 256;
        int row = l >> 2, c = l & 3;
        int rg = bm + row;
        if (rg >= N_TX) rg = 0;
        cp16(abase + (uint32_t)(row * SA2P + c * 4) * 4,
             g_comb + (size_t)rg * COMB_STRIDE + kc + c * 8);
    }
    int kcp = kc >> 1;                  // first k-pair of this tile
#pragma unroll
    for (int i = 0; i < 2; i++) {       // Bh2/Bl2: 16 rows x 32 chunks (16B = 4 u32)
        int l = tid + i * 256;
        int kk = l >> 5, c8 = l & 31;
        cp16(bhbase + (uint32_t)(kk * SBH + c8 * 4) * 4,
             g_w1h2 + (size_t)(kcp + kk) * 128 + c8 * 4);
        cp16(blbase + (uint32_t)(kk * SBH + c8 * 4) * 4,
             g_w1l2 + (size_t)(kcp + kk) * 128 + c8 * 4);
    }
}

__global__ __launch_bounds__(256, 2) void k_h1(const float* __restrict__ b1) {
    extern __shared__ float sm[];
    int tid = threadIdx.x;
    int bm = blockIdx.x * 128;
    uint32_t sbase = (uint32_t)__cvta_generic_to_shared(sm);
    uint32_t aB[2]  = {sbase, sbase + (uint32_t)H1_A_WORDS * 4};
    uint32_t bhB[2] = {sbase + (uint32_t)(2 * H1_A_WORDS) * 4,
                       sbase + (uint32_t)(2 * H1_A_WORDS + H1_B_WORDS) * 4};
    uint32_t blB[2] = {sbase + (uint32_t)(2 * H1_A_WORDS + 2 * H1_B_WORDS) * 4,
                       sbase + (uint32_t)(2 * H1_A_WORDS + 3 * H1_B_WORDS) * 4};
    const uint32_t* Ap[2] = {(const uint32_t*)sm, (const uint32_t*)sm + H1_A_WORDS};
    const uint32_t* Bhp[2] = {(const uint32_t*)sm + 2 * H1_A_WORDS,
                              (const uint32_t*)sm + 2 * H1_A_WORDS + H1_B_WORDS};
    const uint32_t* Blp[2] = {(const uint32_t*)sm + 2 * H1_A_WORDS + 2 * H1_B_WORDS,
                              (const uint32_t*)sm + 2 * H1_A_WORDS + 3 * H1_B_WORDS};

    int lane = tid & 31, wid = tid >> 5;
    int wm = (wid & 3) * 32, wn = (wid >> 2) * 64;
    int l4 = lane >> 2, lq = lane & 3;
    float acc[2][8][4];
#pragma unroll
    for (int mt = 0; mt < 2; mt++)
#pragma unroll
        for (int nt = 0; nt < 8; nt++)
#pragma unroll
            for (int q = 0; q < 4; q++) acc[mt][nt][q] = 0.f;

    h1_stage(aB[0], bhB[0], blB[0], 0, bm, tid);
    CP_COMMIT;

    for (int it = 0; it < NIT; it++) {
        int cur = it & 1;
        CP_WAIT0;
        __syncthreads();
        if (it + 1 < NIT) {
            h1_stage(aB[1 - cur], bhB[1 - cur], blB[1 - cur], (it + 1) * 32, bm, tid);
            CP_COMMIT;
        }
        const uint32_t* Af = Ap[cur];
        const uint32_t* Bhf = Bhp[cur];
        const uint32_t* Blf = Blp[cur];
#pragma unroll
        for (int ks = 0; ks < 2; ks++) {
            int kp = ks * 8;
            uint32_t a[2][4];
#pragma unroll
            for (int mt = 0; mt < 2; mt++) {
                int r = wm + mt * 16 + l4;
                a[mt][0] = Af[r * SA2P + kp + lq];
                a[mt][1] = Af[(r + 8) * SA2P + kp + lq];
                a[mt][2] = Af[r * SA2P + kp + lq + 4];
                a[mt][3] = Af[(r + 8) * SA2P + kp + lq + 4];
            }
#pragma unroll
            for (int nt = 0; nt < 8; nt++) {
                int cb = wn + nt * 8 + l4;
                uint32_t b0h = Bhf[(kp + lq) * SBH + cb];
                uint32_t b1h = Bhf[(kp + 4 + lq) * SBH + cb];
                uint32_t b0l = Blf[(kp + lq) * SBH + cb];
                uint32_t b1l = Blf[(kp + 4 + lq) * SBH + cb];
#pragma unroll
                for (int mt = 0; mt < 2; mt++) {
                    mma16(acc[mt][nt], a[mt], b0h, b1h);
                    mma16(acc[mt][nt], a[mt], b0l, b1l);
                }
            }
        }
        __syncthreads();
    }

#pragma unroll
    for (int mt = 0; mt < 2; mt++)
#pragma unroll
        for (int nt = 0; nt < 8; nt++) {
            int r = bm + wm + mt * 16 + l4;
            int c = wn + nt * 8 + 2 * lq;
            float2 bb = *(const float2*)(b1 + c);
            if (r < N_TX)
                *(float2*)&g_h1[(size_t)r * D + c] =
                    make_float2(fmaxf(acc[mt][nt][0] + bb.x, 0.f),
                                fmaxf(acc[mt][nt][1] + bb.y, 0.f));
            if (r + 8 < N_TX)
                *(float2*)&g_h1[(size_t)(r + 8) * D + c] =
                    make_float2(fmaxf(acc[mt][nt][2] + bb.x, 0.f),
                                fmaxf(acc[mt][nt][3] + bb.y, 0.f));
        }
}

// ================= fused classifier layers 2+3 =================
__global__ void k_h23(const float* __restrict__ w2, const float* __restrict__ b2,
                      const float* __restrict__ w3, const float* __restrict__ b3,
                      float* __restrict__ out) {
    __shared__ float Ws[128 * 64];
    __shared__ float w3s[64];
    int tid = threadIdx.x;
#pragma unroll
    for (int i = 0; i < 8; i++)
        ((float4*)Ws)[tid + i * 256] = ((const float4*)w2)[tid + i * 256];
    if (tid < 64) w3s[tid] = w3[tid];
    __syncthreads();
    int lane = tid & 31, w = tid >> 5;
    for (int rr = 0; rr < 4; rr++) {
        int r = blockIdx.x * 32 + rr * 8 + w;
        if (r >= N_TX) return;
        float4 x = ((const float4*)(g_h1 + (size_t)r * D))[lane];
        float xa[4] = {x.x, x.y, x.z, x.w};
        float a0 = 0.f, a1 = 0.f;
#pragma unroll
        for (int k = 0; k < 128; k++) {
            float xk = __shfl_sync(0xffffffffu, xa[k & 3], k >> 2);
            float2 wv = *(const float2*)&Ws[k * 64 + lane * 2];
            a0 += xk * wv.x;
            a1 += xk * wv.y;
        }
        float2 bb = *(const float2*)&b2[lane * 2];
        float h0 = fmaxf(a0 + bb.x, 0.f);
        float h1v = fmaxf(a1 + bb.y, 0.f);
        float v = h0 * w3s[lane * 2] + h1v * w3s[lane * 2 + 1];
#pragma unroll
        for (int off = 16; off; off >>= 1) v += __shfl_xor_sync(0xffffffffu, v, off);
        if (lane == 0) out[r] = v + b3[0];
    }
}

// ================= launcher =================
extern "C" void kernel_launch(void* const* d_in, const int* in_sizes, int n_in,
                              void* d_out, int out_size) {
    const float* tx_x      = (const float*)d_in[0];
    const float* emb       = (const float*)d_in[1];
    const float* lin_w     = (const float*)d_in[2];
    const float* att_src   = (const float*)d_in[3];
    const float* att_dst   = (const float*)d_in[4];
    const float* conv_bias = (const float*)d_in[5];
    const float* ln_gamma  = (const float*)d_in[6];
    const float* ln_beta   = (const float*)d_in[7];
    const float* w1        = (const float*)d_in[8];
    const float* b1        = (const float*)d_in[9];
    const float* w2        = (const float*)d_in[10];
    const float* b2        = (const float*)d_in[11];
    const float* w3        = (const float*)d_in[12];
    const float* b3        = (const float*)d_in[13];
    const int* entity_idx  = (const int*)d_in[14];
    const int* edge_src    = (const int*)d_in[15];
    const int* edge_dst    = (const int*)d_in[16];
    float* out = (float*)d_out;

    cudaFuncSetAttribute(k_gemm1, cudaFuncAttributeMaxDynamicSharedMemorySize,
                         (128 * SA1 + 2 * 64 * SBH) * 4);
    cudaFuncSetAttribute(k_h1, cudaFuncAttributeMaxDynamicSharedMemorySize,
                         H1_SMEM_W * 4);

    // ---- weight splits (once per launch; deterministic) ----
    k_split_w<<<((COMB_STRIDE / 2) * 128 + 255) / 256, 256>>>(lin_w, w1);

    // ---- CSR build ----
    k_zero_cnt<<<(T * N_ENT + 255) / 256, 256>>>();
    { dim3 g((E_EDGES + 255) / 256, T); k_hist<<<g, 256>>>(edge_dst); }
    { dim3 g(NBLK_SCAN, T); k_scan1<<<g, SCAN_BLK>>>(); }
    k_scan2<<<T, 32>>>();
    { dim3 g(NBLK_SCAN, T); k_scan3<<<g, SCAN_BLK>>>(); }
    { dim3 g((E_EDGES + 255) / 256, T); k_fill<<<g, 256>>>(edge_src, edge_dst); }

    // ---- tx into combined buffer (independent) ----
    k_copytx<<<(N_TX + 7) / 8, 256>>>(tx_x);

    // ---- batched GAT pipeline ----
    { dim3 g((N_ENT + 127) / 128, T);
      k_gemm1<<<g, 256, (128 * SA1 + 2 * 64 * SBH) * 4>>>(emb, entity_idx, att_src, att_dst); }
    { dim3 g((N_ENT + 7) / 8, T); k_gat<<<g, 256>>>(conv_bias, ln_gamma, ln_beta); }
    { dim3 g((N_TX + 7) / 8, T); k_msg<<<g, 256>>>(); }

    // ---- classifier ----
    k_h1<<<(N_TX + 127) / 128, 256, H1_SMEM_W * 4>>>(b1);
    k_h23<<<(N_TX + 31) / 32, 256>>>(w2, b2, w3, b3, out);
}

// round 14
// speedup vs baseline: 1.5532x; 1.0170x over previous
#include <cuda_runtime.h>
#include <cuda_fp16.h>
#include <math.h>
#include <stdint.h>

#define T 11
#define N_ENT 100000
#define N_TX 100000
#define D 128
#define E_EDGES 500000
#define F_TX 394
#define COMB_K 1802
#define COMB_STRIDE 1824
#define NEG_SLOPE 0.2f
#define LN_EPS 1e-5f

#define SCAN_BLK 1024
#define NBLK_SCAN ((N_ENT + SCAN_BLK - 1) / SCAN_BLK)   /* 98 */

// ---------------- scratch (device globals; no allocs allowed) ----------------
__device__ __half g_xw[(size_t)T * N_ENT * D];   // fp16 to halve gather bytes
__device__ float g_as[T * N_ENT];
__device__ float g_ad[T * N_ENT];
__device__ __half g_h[(size_t)T * N_ENT * D];    // fp16
__device__ __half g_comb[(size_t)N_TX * COMB_STRIDE];  // fp16 [msgs 1408 | tx 394 | pad 22]
__device__ float g_h1[(size_t)N_TX * D];

// pre-split fp16 weights in half2 k-pair layout: [k/2][n], pair = (k, k+1) for col n
__device__ uint32_t g_lwh2[64 * 128], g_lwl2[64 * 128];
__device__ uint32_t g_w1h2[(COMB_STRIDE / 2) * 128], g_w1l2[(COMB_STRIDE / 2) * 128];
// exact logit weights: wa_s = W @ att_src, wa_d = W @ att_dst
__device__ float g_was[128], g_wad[128];

__device__ int g_cnt[T * N_ENT];
__device__ int g_off[T * N_ENT];
__device__ int g_cur[T * N_ENT];
__device__ int g_csr[(size_t)T * E_EDGES];
__device__ int g_blksum[T * NBLK_SCAN];

// ---------------- helpers ----------------
__device__ __forceinline__ float leaky(float e) { return (e > 0.f) ? e : e * NEG_SLOPE; }

#define FMA4(ACC, S, B) \
    (ACC).x += (S) * (B).x; (ACC).y += (S) * (B).y; \
    (ACC).z += (S) * (B).z; (ACC).w += (S) * (B).w;

__device__ __forceinline__ float4 ld_half4(const __half* row, int lane) {
    uint2 p = ((const uint2*)row)[lane];
    float2 lo = __half22float2(*(__half2*)&p.x);
    float2 hi = __half22float2(*(__half2*)&p.y);
    return make_float4(lo.x, lo.y, hi.x, hi.y);
}
__device__ __forceinline__ void st_half4(__half* row, int lane, float4 v) {
    __half2 h0 = __floats2half2_rn(v.x, v.y);
    __half2 h1 = __floats2half2_rn(v.z, v.w);
    uint2 p;
    p.x = *(uint32_t*)&h0;
    p.y = *(uint32_t*)&h1;
    ((uint2*)row)[lane] = p;
}

__device__ __forceinline__ void cp16(uint32_t s, const void* g) {
    asm volatile("cp.async.cg.shared.global [%0], [%1], 16;" :: "r"(s), "l"(g));
}
#define CP_COMMIT asm volatile("cp.async.commit_group;")
#define CP_WAIT0  asm volatile("cp.async.wait_group 0;")

// fp16 m16n8k16 mma, fp32 accumulate
__device__ __forceinline__ void mma16(float* c, const uint32_t* a, uint32_t b0, uint32_t b1) {
    asm volatile(
        "mma.sync.aligned.m16n8k16.row.col.f32.f16.f16.f32 "
        "{%0,%1,%2,%3}, {%4,%5,%6,%7}, {%8,%9}, {%0,%1,%2,%3};"
        : "+f"(c[0]), "+f"(c[1]), "+f"(c[2]), "+f"(c[3])
        : "r"(a[0]), "r"(a[1]), "r"(a[2]), "r"(a[3]), "r"(b0), "r"(b1));
}

// pack float pair into half2 (hi only)
__device__ __forceinline__ uint32_t h2pack(float x, float y) {
    __half2 h = __floats2half2_rn(x, y);
    return *(uint32_t*)&h;
}
// split a float pair into hi/lo half2
__device__ __forceinline__ void h2split(float x, float y, uint32_t& hi, uint32_t& lo) {
    __half2 h = __floats2half2_rn(x, y);
    float2 hf = __half22float2(h);
    __half2 l = __floats2half2_rn(x - hf.x, y - hf.y);
    hi = *(uint32_t*)&h;
    lo = *(uint32_t*)&l;
}

// ================= weight splitting + logit-vector precompute (once) =================
__global__ void k_split_w(const float* __restrict__ W, const float* __restrict__ w1,
                          const float* __restrict__ att_s, const float* __restrict__ att_d) {
    int i = blockIdx.x * blockDim.x + threadIdx.x;
    if (i < 128) {          // wa_s[k] = sum_c W[k][c] * att_s[c]  (exact fp32)
        float ss = 0.f, dd = 0.f;
        const float* wr = W + i * 128;
        for (int c = 0; c < 128; c++) {
            ss += wr[c] * att_s[c];
            dd += wr[c] * att_d[c];
        }
        g_was[i] = ss;
        g_wad[i] = dd;
    }
    if (i < 64 * 128) {
        int p = i >> 7, c = i & 127;
        uint32_t h, l;
        h2split(W[(2 * p) * 128 + c], W[(2 * p + 1) * 128 + c], h, l);
        g_lwh2[i] = h; g_lwl2[i] = l;
    }
    if (i < (COMB_STRIDE / 2) * 128) {
        int p = i >> 7, c = i & 127;
        int ck0 = 2 * p, ck1 = 2 * p + 1;
        float v0 = 0.f, v1 = 0.f;
        if (ck0 < 1408)          v0 = w1[(size_t)(394 + ck0) * 128 + c];
        else if (ck0 < COMB_K)   v0 = w1[(size_t)(ck0 - 1408) * 128 + c];
        if (ck1 < 1408)          v1 = w1[(size_t)(394 + ck1) * 128 + c];
        else if (ck1 < COMB_K)   v1 = w1[(size_t)(ck1 - 1408) * 128 + c];
        uint32_t h, l;
        h2split(v0, v1, h, l);
        g_w1h2[i] = h; g_w1l2[i] = l;
    }
}

// ================= CSR build =================
__global__ void k_zero_cnt() {
    int i = blockIdx.x * blockDim.x + threadIdx.x;
    if (i < T * N_ENT) g_cnt[i] = 0;
}
__global__ void k_hist(const int* __restrict__ dst) {
    int t = blockIdx.y;
    int i = blockIdx.x * blockDim.x + threadIdx.x;
    if (i < E_EDGES) atomicAdd(&g_cnt[t * N_ENT + dst[(size_t)t * E_EDGES + i]], 1);
}
__global__ void k_scan1() {
    __shared__ int s[SCAN_BLK];
    int t = blockIdx.y, tid = threadIdx.x;
    int idx = blockIdx.x * SCAN_BLK + tid;
    int v = (idx < N_ENT) ? g_cnt[t * N_ENT + idx] : 0;
    s[tid] = v;
    __syncthreads();
#pragma unroll
    for (int off = 1; off < SCAN_BLK; off <<= 1) {
        int y = (tid >= off) ? s[tid - off] : 0;
        __syncthreads();
        s[tid] += y;
        __syncthreads();
    }
    if (idx < N_ENT) g_off[t * N_ENT + idx] = s[tid] - v;
    if (tid == SCAN_BLK - 1) g_blksum[t * NBLK_SCAN + blockIdx.x] = s[tid];
}
__global__ void k_scan2() {
    int t = blockIdx.x;
    if (threadIdx.x == 0) {
        int run = 0;
        for (int b = 0; b < NBLK_SCAN; b++) {
            int v = g_blksum[t * NBLK_SCAN + b];
            g_blksum[t * NBLK_SCAN + b] = run;
            run += v;
        }
    }
}
__global__ void k_scan3() {
    int t = blockIdx.y;
    int idx = blockIdx.x * SCAN_BLK + threadIdx.x;
    if (idx < N_ENT) {
        int v = g_off[t * N_ENT + idx] + g_blksum[t * NBLK_SCAN + blockIdx.x];
        g_off[t * N_ENT + idx] = v;
        g_cur[t * N_ENT + idx] = v;
    }
}
__global__ void k_fill(const int* __restrict__ src, const int* __restrict__ dst) {
    int t = blockIdx.y;
    int i = blockIdx.x * blockDim.x + threadIdx.x;
    if (i < E_EDGES) {
        int d = dst[(size_t)t * E_EDGES + i];
        int pos = atomicAdd(&g_cur[t * N_ENT + d], 1);
        g_csr[(size_t)t * E_EDGES + pos] = src[(size_t)t * E_EDGES + i];
    }
}

// ================= copy tx into combined buffer (fp16) =================
__global__ void k_copytx(const float* __restrict__ tx) {
    int r = blockIdx.x * 8 + (threadIdx.x >> 5);
    if (r >= N_TX) return;
    int lane = threadIdx.x & 31;
    __half* drow = g_comb + (size_t)r * COMB_STRIDE + 1408;
    const float* srow = tx + (size_t)r * F_TX;
    for (int c = lane; c < F_TX; c += 32) drow[c] = __float2half_rn(srow[c]);
    int p = F_TX + lane;
    if (p < COMB_STRIDE - 1408) drow[p] = __float2half_rn(0.f);
}

// ================= GEMM1 (2-term fp16 mma + exact fp32 logits) =================
#define SA1 132
#define SBH 136   /* B smem stride in half2 units */
__global__ __launch_bounds__(256, 1) void k_gemm1(
    const float* __restrict__ emb, const int* __restrict__ eidx) {
    extern __shared__ float sm[];
    float* As = sm;                                       // [128][132] floats
    uint32_t* Bh2 = (uint32_t*)(sm + 128 * SA1);          // [64][136] half2
    uint32_t* Bl2 = Bh2 + 64 * SBH;
    int t = blockIdx.y;
    const float* embt = emb + (size_t)t * N_ENT * D;
    const int* idxt = eidx + (size_t)t * N_ENT;
    int tid = threadIdx.x;
    int bm = blockIdx.x * 128;
    uint32_t sbase = (uint32_t)__cvta_generic_to_shared(sm);
    uint32_t bhbase = sbase + (uint32_t)(128 * SA1) * 4;
    uint32_t blbase = bhbase + (uint32_t)(64 * SBH) * 4;

#pragma unroll
    for (int i = 0; i < 8; i++) {       // stage Bh2/Bl2: 64 rows x 32 chunks (16B = 4 u32)
        int l = tid + i * 256;
        int row = l >> 5, c8 = l & 31;
        cp16(bhbase + (uint32_t)(row * SBH + c8 * 4) * 4, g_lwh2 + row * 128 + c8 * 4);
        cp16(blbase + (uint32_t)(row * SBH + c8 * 4) * 4, g_lwl2 + row * 128 + c8 * 4);
    }
#pragma unroll
    for (int i = 0; i < 16; i++) {      // stage A (gathered rows)
        int l = tid + i * 256;
        int row = l >> 5, c4 = l & 31;
        int rg = bm + row;
        int srcr = (rg < N_ENT) ? idxt[rg] : 0;
        cp16(sbase + (uint32_t)(row * SA1 + 4 * c4) * 4, embt + (size_t)srcr * D + 4 * c4);
    }
    CP_COMMIT; CP_WAIT0;
    __syncthreads();

    int lane = tid & 31, wid = tid >> 5;

    // ---- exact logits from staged fp32 emb rows ----
    {
        float4 ws4 = ((const float4*)g_was)[lane];
        float4 wd4 = ((const float4*)g_wad)[lane];
        for (int i = 0; i < 16; i++) {
            int row = wid * 16 + i;
            int rg = bm + row;
            if (rg >= N_ENT) break;
            float4 x = *(float4*)&As[row * SA1 + 4 * lane];
            float s = x.x * ws4.x + x.y * ws4.y + x.z * ws4.z + x.w * ws4.w;
            float d = x.x * wd4.x + x.y * wd4.y + x.z * wd4.z + x.w * wd4.w;
#pragma unroll
            for (int off = 16; off; off >>= 1) {
                s += __shfl_xor_sync(0xffffffffu, s, off);
                d += __shfl_xor_sync(0xffffffffu, d, off);
            }
            if (lane == 0) { g_as[t * N_ENT + rg] = s; g_ad[t * N_ENT + rg] = d; }
        }
    }

    int wm = (wid & 3) * 32, wn = (wid >> 2) * 64;
    int l4 = lane >> 2, lq = lane & 3;
    float acc[2][8][4];
#pragma unroll
    for (int mt = 0; mt < 2; mt++)
#pragma unroll
        for (int nt = 0; nt < 8; nt++)
#pragma unroll
            for (int q = 0; q < 4; q++) acc[mt][nt][q] = 0.f;

    for (int k0 = 0; k0 < 128; k0 += 16) {
        uint32_t ah[2][4];
#pragma unroll
        for (int mt = 0; mt < 2; mt++) {
            int r = wm + mt * 16 + l4;
            float2 x0 = *(const float2*)&As[r * SA1 + k0 + 2 * lq];
            float2 x1 = *(const float2*)&As[(r + 8) * SA1 + k0 + 2 * lq];
            float2 x2 = *(const float2*)&As[r * SA1 + k0 + 8 + 2 * lq];
            float2 x3 = *(const float2*)&As[(r + 8) * SA1 + k0 + 8 + 2 * lq];
            ah[mt][0] = h2pack(x0.x, x0.y);
            ah[mt][1] = h2pack(x1.x, x1.y);
            ah[mt][2] = h2pack(x2.x, x2.y);
            ah[mt][3] = h2pack(x3.x, x3.y);
        }
        int kp = k0 >> 1;
#pragma unroll
        for (int nt = 0; nt < 8; nt++) {
            int cb = wn + nt * 8 + l4;
            uint32_t b0h = Bh2[(kp + lq) * SBH + cb];
            uint32_t b1h = Bh2[(kp + 4 + lq) * SBH + cb];
            uint32_t b0l = Bl2[(kp + lq) * SBH + cb];
            uint32_t b1l = Bl2[(kp + 4 + lq) * SBH + cb];
#pragma unroll
            for (int mt = 0; mt < 2; mt++) {
                mma16(acc[mt][nt], ah[mt], b0h, b1h);
                mma16(acc[mt][nt], ah[mt], b0l, b1l);
            }
        }
    }
    __syncthreads();
    float* Cs = As;   // reuse
#pragma unroll
    for (int mt = 0; mt < 2; mt++)
#pragma unroll
        for (int nt = 0; nt < 8; nt++) {
            int r = wm + mt * 16 + l4;
            int c = wn + nt * 8 + 2 * lq;
            *(float2*)&Cs[r * SA1 + c] = make_float2(acc[mt][nt][0], acc[mt][nt][1]);
            *(float2*)&Cs[(r + 8) * SA1 + c] = make_float2(acc[mt][nt][2], acc[mt][nt][3]);
        }
    __syncthreads();

    for (int i = 0; i < 16; i++) {
        int row = wid * 16 + i;
        int rg = bm + row;
        if (rg >= N_ENT) break;
        float4 v = *(float4*)&Cs[row * SA1 + 4 * lane];
        st_half4(g_xw + ((size_t)t * N_ENT + rg) * D, lane, v);
    }
}

// ================= fused GAT: single-pass softmax+aggregate + bias + LN =================
__global__ void k_gat(const float* __restrict__ conv_bias,
                      const float* __restrict__ gamma_all, const float* __restrict__ beta_all) {
    int t = blockIdx.y;
    int dn = blockIdx.x * 8 + (threadIdx.x >> 5);
    if (dn >= N_ENT) return;
    int lane = threadIdx.x & 31;
    const float* asv = g_as + t * N_ENT;
    float ad = g_ad[t * N_ENT + dn];
    int off0 = g_off[t * N_ENT + dn];
    int off1 = (dn + 1 < N_ENT) ? g_off[t * N_ENT + dn + 1] : E_EDGES;
    const int* csr = g_csr + (size_t)t * E_EDGES;
    const __half* xw = g_xw + (size_t)t * N_ENT * D;

    float ex_self = __expf(leaky(asv[dn] + ad));
    float wsum = ex_self;
    float4 vs = ld_half4(xw + (size_t)dn * D, lane);
    float4 acc = make_float4(ex_self * vs.x, ex_self * vs.y, ex_self * vs.z, ex_self * vs.w);

    for (int j = off0; j < off1; j++) {
        int s = csr[j];
        float e = __expf(leaky(asv[s] + ad));
        float4 v = ld_half4(xw + (size_t)s * D, lane);
        FMA4(acc, e, v);
        wsum += e;
    }
    float inv = 1.f / (wsum + 1e-16f);
    acc.x *= inv; acc.y *= inv; acc.z *= inv; acc.w *= inv;

    float4 cb = ((const float4*)conv_bias)[lane];
    acc.x += cb.x; acc.y += cb.y; acc.z += cb.z; acc.w += cb.w;
    float sum = acc.x + acc.y + acc.z + acc.w;
#pragma unroll
    for (int off = 16; off; off >>= 1) sum += __shfl_xor_sync(0xffffffffu, sum, off);
    float mu = sum * (1.f / D);
    float4 dd = make_float4(acc.x - mu, acc.y - mu, acc.z - mu, acc.w - mu);
    float sq = dd.x * dd.x + dd.y * dd.y + dd.z * dd.z + dd.w * dd.w;
#pragma unroll
    for (int off = 16; off; off >>= 1) sq += __shfl_xor_sync(0xffffffffu, sq, off);
    float invs = rsqrtf(sq * (1.f / D) + LN_EPS);
    float4 gm = ((const float4*)(gamma_all + t * D))[lane];
    float4 bt = ((const float4*)(beta_all + t * D))[lane];
    float4 h;
    h.x = dd.x * invs * gm.x + bt.x;
    h.y = dd.y * invs * gm.y + bt.y;
    h.z = dd.z * invs * gm.z + bt.z;
    h.w = dd.w * invs * gm.w + bt.w;
    st_half4(g_h + ((size_t)t * N_ENT + dn) * D, lane, h);
}

// ================= msg gather into combined buffer (fp16 out) =================
__global__ void k_msg() {
    int t = blockIdx.y;
    int dn = blockIdx.x * 8 + (threadIdx.x >> 5);
    if (dn >= N_TX) return;
    int lane = threadIdx.x & 31;
    int off0 = g_off[t * N_ENT + dn];
    int off1 = (dn + 1 < N_ENT) ? g_off[t * N_ENT + dn + 1] : E_EDGES;
    const int* csr = g_csr + (size_t)t * E_EDGES;
    const __half* h = g_h + (size_t)t * N_ENT * D;
    float4 acc = make_float4(0.f, 0.f, 0.f, 0.f);
    for (int j = off0; j < off1; j++) {
        float4 v = ld_half4(h + (size_t)csr[j] * D, lane);
        acc.x += v.x; acc.y += v.y; acc.z += v.z; acc.w += v.w;
    }
    st_half4(g_comb + (size_t)dn * COMB_STRIDE + t * D, lane, acc);
}

// ================= classifier layer 1 (A fp16 direct + 2-term B-split mma) =================
#define SA2P 20   /* A smem stride in half2 (u32) units: 16 pairs + 4 pad */
#define NIT 57    /* 1824 / 32 */
#define H1_A_WORDS   (128 * SA2P)        /* 2560 u32 per stage */
#define H1_B_WORDS   (16 * SBH)          /* 2176 u32 per plane */
#define H1_SMEM_W    (2 * H1_A_WORDS + 4 * H1_B_WORDS)   /* 13824 u32 = 55 KB */

__device__ __forceinline__ void h1_stage(uint32_t abase, uint32_t bhbase, uint32_t blbase,
                                         int kc, int bm, int tid) {
#pragma unroll
    for (int i = 0; i < 2; i++) {       // A: 128 rows x 4 chunks (16B = 8 halves)
        int l = tid + i * 256;
        int row = l >> 2, c = l & 3;
        int rg = bm + row;
        if (rg >= N_TX) rg = 0;
        cp16(abase + (uint32_t)(row * SA2P + c * 4) * 4,
             g_comb + (size_t)rg * COMB_STRIDE + kc + c * 8);
    }
    int kcp = kc >> 1;                  // first k-pair of this tile
#pragma unroll
    for (int i = 0; i < 2; i++) {       // Bh2/Bl2: 16 rows x 32 chunks (16B = 4 u32)
        int l = tid + i * 256;
        int kk = l >> 5, c8 = l & 31;
        cp16(bhbase + (uint32_t)(kk * SBH + c8 * 4) * 4,
             g_w1h2 + (size_t)(kcp + kk) * 128 + c8 * 4);
        cp16(blbase + (uint32_t)(kk * SBH + c8 * 4) * 4,
             g_w1l2 + (size_t)(kcp + kk) * 128 + c8 * 4);
    }
}

__global__ __launch_bounds__(256, 2) void k_h1(const float* __restrict__ b1) {
    extern __shared__ float sm[];
    int tid = threadIdx.x;
    int bm = blockIdx.x * 128;
    uint32_t sbase = (uint32_t)__cvta_generic_to_shared(sm);
    uint32_t aB[2]  = {sbase, sbase + (uint32_t)H1_A_WORDS * 4};
    uint32_t bhB[2] = {sbase + (uint32_t)(2 * H1_A_WORDS) * 4,
                       sbase + (uint32_t)(2 * H1_A_WORDS + H1_B_WORDS) * 4};
    uint32_t blB[2] = {sbase + (uint32_t)(2 * H1_A_WORDS + 2 * H1_B_WORDS) * 4,
                       sbase + (uint32_t)(2 * H1_A_WORDS + 3 * H1_B_WORDS) * 4};
    const uint32_t* Ap[2] = {(const uint32_t*)sm, (const uint32_t*)sm + H1_A_WORDS};
    const uint32_t* Bhp[2] = {(const uint32_t*)sm + 2 * H1_A_WORDS,
                              (const uint32_t*)sm + 2 * H1_A_WORDS + H1_B_WORDS};
    const uint32_t* Blp[2] = {(const uint32_t*)sm + 2 * H1_A_WORDS + 2 * H1_B_WORDS,
                              (const uint32_t*)sm + 2 * H1_A_WORDS + 3 * H1_B_WORDS};

    int lane = tid & 31, wid = tid >> 5;
    int wm = (wid & 3) * 32, wn = (wid >> 2) * 64;
    int l4 = lane >> 2, lq = lane & 3;
    float acc[2][8][4];
#pragma unroll
    for (int mt = 0; mt < 2; mt++)
#pragma unroll
        for (int nt = 0; nt < 8; nt++)
#pragma unroll
            for (int q = 0; q < 4; q++) acc[mt][nt][q] = 0.f;

    h1_stage(aB[0], bhB[0], blB[0], 0, bm, tid);
    CP_COMMIT;

    for (int it = 0; it < NIT; it++) {
        int cur = it & 1;
        CP_WAIT0;
        __syncthreads();
        if (it + 1 < NIT) {
            h1_stage(aB[1 - cur], bhB[1 - cur], blB[1 - cur], (it + 1) * 32, bm, tid);
            CP_COMMIT;
        }
        const uint32_t* Af = Ap[cur];
        const uint32_t* Bhf = Bhp[cur];
        const uint32_t* Blf = Blp[cur];
#pragma unroll
        for (int ks = 0; ks < 2; ks++) {
            int kp = ks * 8;
            uint32_t a[2][4];
#pragma unroll
            for (int mt = 0; mt < 2; mt++) {
                int r = wm + mt * 16 + l4;
                a[mt][0] = Af[r * SA2P + kp + lq];
                a[mt][1] = Af[(r + 8) * SA2P + kp + lq];
                a[mt][2] = Af[r * SA2P + kp + lq + 4];
                a[mt][3] = Af[(r + 8) * SA2P + kp + lq + 4];
            }
#pragma unroll
            for (int nt = 0; nt < 8; nt++) {
                int cb = wn + nt * 8 + l4;
                uint32_t b0h = Bhf[(kp + lq) * SBH + cb];
                uint32_t b1h = Bhf[(kp + 4 + lq) * SBH + cb];
                uint32_t b0l = Blf[(kp + lq) * SBH + cb];
                uint32_t b1l = Blf[(kp + 4 + lq) * SBH + cb];
#pragma unroll
                for (int mt = 0; mt < 2; mt++) {
                    mma16(acc[mt][nt], a[mt], b0h, b1h);
                    mma16(acc[mt][nt], a[mt], b0l, b1l);
                }
            }
        }
        __syncthreads();
    }

#pragma unroll
    for (int mt = 0; mt < 2; mt++)
#pragma unroll
        for (int nt = 0; nt < 8; nt++) {
            int r = bm + wm + mt * 16 + l4;
            int c = wn + nt * 8 + 2 * lq;
            float2 bb = *(const float2*)(b1 + c);
            if (r < N_TX)
                *(float2*)&g_h1[(size_t)r * D + c] =
                    make_float2(fmaxf(acc[mt][nt][0] + bb.x, 0.f),
                                fmaxf(acc[mt][nt][1] + bb.y, 0.f));
            if (r + 8 < N_TX)
                *(float2*)&g_h1[(size_t)(r + 8) * D + c] =
                    make_float2(fmaxf(acc[mt][nt][2] + bb.x, 0.f),
                                fmaxf(acc[mt][nt][3] + bb.y, 0.f));
        }
}

// ================= fused classifier layers 2+3 =================
__global__ void k_h23(const float* __restrict__ w2, const float* __restrict__ b2,
                      const float* __restrict__ w3, const float* __restrict__ b3,
                      float* __restrict__ out) {
    __shared__ float Ws[128 * 64];
    __shared__ float w3s[64];
    int tid = threadIdx.x;
#pragma unroll
    for (int i = 0; i < 8; i++)
        ((float4*)Ws)[tid + i * 256] = ((const float4*)w2)[tid + i * 256];
    if (tid < 64) w3s[tid] = w3[tid];
    __syncthreads();
    int lane = tid & 31, w = tid >> 5;
    for (int rr = 0; rr < 4; rr++) {
        int r = blockIdx.x * 32 + rr * 8 + w;
        if (r >= N_TX) return;
        float4 x = ((const float4*)(g_h1 + (size_t)r * D))[lane];
        float xa[4] = {x.x, x.y, x.z, x.w};
        float a0 = 0.f, a1 = 0.f;
#pragma unroll
        for (int k = 0; k < 128; k++) {
            float xk = __shfl_sync(0xffffffffu, xa[k & 3], k >> 2);
            float2 wv = *(const float2*)&Ws[k * 64 + lane * 2];
            a0 += xk * wv.x;
            a1 += xk * wv.y;
        }
        float2 bb = *(const float2*)&b2[lane * 2];
        float h0 = fmaxf(a0 + bb.x, 0.f);
        float h1v = fmaxf(a1 + bb.y, 0.f);
        float v = h0 * w3s[lane * 2] + h1v * w3s[lane * 2 + 1];
#pragma unroll
        for (int off = 16; off; off >>= 1) v += __shfl_xor_sync(0xffffffffu, v, off);
        if (lane == 0) out[r] = v + b3[0];
    }
}

// ================= launcher =================
extern "C" void kernel_launch(void* const* d_in, const int* in_sizes, int n_in,
                              void* d_out, int out_size) {
    const float* tx_x      = (const float*)d_in[0];
    const float* emb       = (const float*)d_in[1];
    const float* lin_w     = (const float*)d_in[2];
    const float* att_src   = (const float*)d_in[3];
    const float* att_dst   = (const float*)d_in[4];
    const float* conv_bias = (const float*)d_in[5];
    const float* ln_gamma  = (const float*)d_in[6];
    const float* ln_beta   = (const float*)d_in[7];
    const float* w1        = (const float*)d_in[8];
    const float* b1        = (const float*)d_in[9];
    const float* w2        = (const float*)d_in[10];
    const float* b2        = (const float*)d_in[11];
    const float* w3        = (const float*)d_in[12];
    const float* b3        = (const float*)d_in[13];
    const int* entity_idx  = (const int*)d_in[14];
    const int* edge_src    = (const int*)d_in[15];
    const int* edge_dst    = (const int*)d_in[16];
    float* out = (float*)d_out;

    cudaFuncSetAttribute(k_gemm1, cudaFuncAttributeMaxDynamicSharedMemorySize,
                         (128 * SA1 + 2 * 64 * SBH) * 4);
    cudaFuncSetAttribute(k_h1, cudaFuncAttributeMaxDynamicSharedMemorySize,
                         H1_SMEM_W * 4);

    // ---- weight splits + exact logit vectors (once per launch; deterministic) ----
    k_split_w<<<((COMB_STRIDE / 2) * 128 + 255) / 256, 256>>>(lin_w, w1, att_src, att_dst);

    // ---- CSR build ----
    k_zero_cnt<<<(T * N_ENT + 255) / 256, 256>>>();
    { dim3 g((E_EDGES + 255) / 256, T); k_hist<<<g, 256>>>(edge_dst); }
    { dim3 g(NBLK_SCAN, T); k_scan1<<<g, SCAN_BLK>>>(); }
    k_scan2<<<T, 32>>>();
    { dim3 g(NBLK_SCAN, T); k_scan3<<<g, SCAN_BLK>>>(); }
    { dim3 g((E_EDGES + 255) / 256, T); k_fill<<<g, 256>>>(edge_src, edge_dst); }

    // ---- tx into combined buffer (independent) ----
    k_copytx<<<(N_TX + 7) / 8, 256>>>(tx_x);

    // ---- batched GAT pipeline ----
    { dim3 g((N_ENT + 127) / 128, T);
      k_gemm1<<<g, 256, (128 * SA1 + 2 * 64 * SBH) * 4>>>(emb, entity_idx); }
    { dim3 g((N_ENT + 7) / 8, T); k_gat<<<g, 256>>>(conv_bias, ln_gamma, ln_beta); }
    { dim3 g((N_TX + 7) / 8, T); k_msg<<<g, 256>>>(); }

    // ---- classifier ----
    k_h1<<<(N_TX + 127) / 128, 256, H1_SMEM_W * 4>>>(b1);
    k_h23<<<(N_TX + 31) / 32, 256>>>(w2, b2, w3, b3, out);
}

// round 16
// speedup vs baseline: 1.5988x; 1.0293x over previous
#include <cuda_runtime.h>
#include <cuda_fp16.h>
#include <math.h>
#include <stdint.h>

#define T 11
#define N_ENT 100000
#define N_TX 100000
#define D 128
#define E_EDGES 500000
#define F_TX 394
#define COMB_K 1802
#define COMB_STRIDE 1824
#define NEG_SLOPE 0.2f
#define LN_EPS 1e-5f

#define SCAN_BLK 1024
#define NBLK_SCAN ((N_ENT + SCAN_BLK - 1) / SCAN_BLK)   /* 98 */

// ---------------- scratch (device globals; no allocs allowed) ----------------
__device__ __half g_xw[(size_t)T * N_ENT * D];
__device__ float g_as[T * N_ENT];
__device__ float g_ad[T * N_ENT];
__device__ __half g_h[(size_t)T * N_ENT * D];
__device__ __half g_comb[(size_t)N_TX * COMB_STRIDE];  // fp16 [msgs 1408 | tx 394 | pad 22]

// pre-split fp16 weights in half2 k-pair layout: [k/2][n]
__device__ uint32_t g_lwh2[64 * 128], g_lwl2[64 * 128];
__device__ uint32_t g_w1h2[(COMB_STRIDE / 2) * 128], g_w1l2[(COMB_STRIDE / 2) * 128];
// exact logit weights: wa_s = W @ att_src, wa_d = W @ att_dst
__device__ float g_was[128], g_wad[128];

__device__ int g_cnt[T * N_ENT];
__device__ int g_off[T * N_ENT];
__device__ int g_cur[T * N_ENT];
__device__ int g_csr[(size_t)T * E_EDGES];
__device__ int g_blksum[T * NBLK_SCAN];

// ---------------- helpers ----------------
__device__ __forceinline__ float leaky(float e) { return (e > 0.f) ? e : e * NEG_SLOPE; }

#define FMA4(ACC, S, B) \
    (ACC).x += (S) * (B).x; (ACC).y += (S) * (B).y; \
    (ACC).z += (S) * (B).z; (ACC).w += (S) * (B).w;

__device__ __forceinline__ float4 ld_half4(const __half* row, int lane) {
    uint2 p = ((const uint2*)row)[lane];
    float2 lo = __half22float2(*(__half2*)&p.x);
    float2 hi = __half22float2(*(__half2*)&p.y);
    return make_float4(lo.x, lo.y, hi.x, hi.y);
}
__device__ __forceinline__ void st_half4(__half* row, int lane, float4 v) {
    __half2 h0 = __floats2half2_rn(v.x, v.y);
    __half2 h1 = __floats2half2_rn(v.z, v.w);
    uint2 p;
    p.x = *(uint32_t*)&h0;
    p.y = *(uint32_t*)&h1;
    ((uint2*)row)[lane] = p;
}

__device__ __forceinline__ void cp16(uint32_t s, const void* g) {
    asm volatile("cp.async.cg.shared.global [%0], [%1], 16;" :: "r"(s), "l"(g));
}
#define CP_COMMIT asm volatile("cp.async.commit_group;")
#define CP_WAIT0  asm volatile("cp.async.wait_group 0;")

// fp16 m16n8k16 mma, fp32 accumulate
__device__ __forceinline__ void mma16(float* c, const uint32_t* a, uint32_t b0, uint32_t b1) {
    asm volatile(
        "mma.sync.aligned.m16n8k16.row.col.f32.f16.f16.f32 "
        "{%0,%1,%2,%3}, {%4,%5,%6,%7}, {%8,%9}, {%0,%1,%2,%3};"
        : "+f"(c[0]), "+f"(c[1]), "+f"(c[2]), "+f"(c[3])
        : "r"(a[0]), "r"(a[1]), "r"(a[2]), "r"(a[3]), "r"(b0), "r"(b1));
}

__device__ __forceinline__ uint32_t h2pack(float x, float y) {
    __half2 h = __floats2half2_rn(x, y);
    return *(uint32_t*)&h;
}
__device__ __forceinline__ void h2split(float x, float y, uint32_t& hi, uint32_t& lo) {
    __half2 h = __floats2half2_rn(x, y);
    float2 hf = __half22float2(h);
    __half2 l = __floats2half2_rn(x - hf.x, y - hf.y);
    hi = *(uint32_t*)&h;
    lo = *(uint32_t*)&l;
}

// ================= weight splitting + logit-vector precompute (once) =================
__global__ void k_split_w(const float* __restrict__ W, const float* __restrict__ w1,
                          const float* __restrict__ att_s, const float* __restrict__ att_d) {
    int i = blockIdx.x * blockDim.x + threadIdx.x;
    if (i < 128) {
        float ss = 0.f, dd = 0.f;
        const float* wr = W + i * 128;
        for (int c = 0; c < 128; c++) {
            ss += wr[c] * att_s[c];
            dd += wr[c] * att_d[c];
        }
        g_was[i] = ss;
        g_wad[i] = dd;
    }
    if (i < 64 * 128) {
        int p = i >> 7, c = i & 127;
        uint32_t h, l;
        h2split(W[(2 * p) * 128 + c], W[(2 * p + 1) * 128 + c], h, l);
        g_lwh2[i] = h; g_lwl2[i] = l;
    }
    if (i < (COMB_STRIDE / 2) * 128) {
        int p = i >> 7, c = i & 127;
        int ck0 = 2 * p, ck1 = 2 * p + 1;
        float v0 = 0.f, v1 = 0.f;
        if (ck0 < 1408)          v0 = w1[(size_t)(394 + ck0) * 128 + c];
        else if (ck0 < COMB_K)   v0 = w1[(size_t)(ck0 - 1408) * 128 + c];
        if (ck1 < 1408)          v1 = w1[(size_t)(394 + ck1) * 128 + c];
        else if (ck1 < COMB_K)   v1 = w1[(size_t)(ck1 - 1408) * 128 + c];
        uint32_t h, l;
        h2split(v0, v1, h, l);
        g_w1h2[i] = h; g_w1l2[i] = l;
    }
}

// ================= CSR build =================
__global__ void k_zero_cnt() {
    int i = blockIdx.x * blockDim.x + threadIdx.x;
    if (i < T * N_ENT) g_cnt[i] = 0;
}
__global__ void k_hist(const int* __restrict__ dst) {
    int t = blockIdx.y;
    int i = blockIdx.x * blockDim.x + threadIdx.x;
    if (i < E_EDGES) atomicAdd(&g_cnt[t * N_ENT + dst[(size_t)t * E_EDGES + i]], 1);
}
__global__ void k_scan1() {
    __shared__ int s[SCAN_BLK];
    int t = blockIdx.y, tid = threadIdx.x;
    int idx = blockIdx.x * SCAN_BLK + tid;
    int v = (idx < N_ENT) ? g_cnt[t * N_ENT + idx] : 0;
    s[tid] = v;
    __syncthreads();
#pragma unroll
    for (int off = 1; off < SCAN_BLK; off <<= 1) {
        int y = (tid >= off) ? s[tid - off] : 0;
        __syncthreads();
        s[tid] += y;
        __syncthreads();
    }
    if (idx < N_ENT) g_off[t * N_ENT + idx] = s[tid] - v;
    if (tid == SCAN_BLK - 1) g_blksum[t * NBLK_SCAN + blockIdx.x] = s[tid];
}
// fused scan2+scan3: each block computes the 98-entry block prefix locally
__global__ void k_scan23() {
    __shared__ int bs[NBLK_SCAN];
    int t = blockIdx.y, tid = threadIdx.x;
    if (tid < NBLK_SCAN) bs[tid] = g_blksum[t * NBLK_SCAN + tid];
    __syncthreads();
    if (tid == 0) {
        int run = 0;
        for (int b = 0; b < NBLK_SCAN; b++) { int v = bs[b]; bs[b] = run; run += v; }
    }
    __syncthreads();
    int idx = blockIdx.x * SCAN_BLK + tid;
    if (idx < N_ENT) {
        int v = g_off[t * N_ENT + idx] + bs[blockIdx.x];
        g_off[t * N_ENT + idx] = v;
        g_cur[t * N_ENT + idx] = v;
    }
}
__global__ void k_fill(const int* __restrict__ src, const int* __restrict__ dst) {
    int t = blockIdx.y;
    int i = blockIdx.x * blockDim.x + threadIdx.x;
    if (i < E_EDGES) {
        int d = dst[(size_t)t * E_EDGES + i];
        int pos = atomicAdd(&g_cur[t * N_ENT + d], 1);
        g_csr[(size_t)t * E_EDGES + pos] = src[(size_t)t * E_EDGES + i];
    }
}

// ================= copy tx into combined buffer (fp16) =================
__global__ void k_copytx(const float* __restrict__ tx) {
    int r = blockIdx.x * 8 + (threadIdx.x >> 5);
    if (r >= N_TX) return;
    int lane = threadIdx.x & 31;
    __half* drow = g_comb + (size_t)r * COMB_STRIDE + 1408;
    const float* srow = tx + (size_t)r * F_TX;
    for (int c = lane; c < F_TX; c += 32) drow[c] = __float2half_rn(srow[c]);
    int p = F_TX + lane;
    if (p < COMB_STRIDE - 1408) drow[p] = __float2half_rn(0.f);
}

// ================= GEMM1 v2: occ-2, smem time-multiplex, direct fragment stores =================
#define SA1F 132                    /* fp32 A stride (floats) */
#define SAH  68                     /* packed fp16 A stride (u32 k-pairs) */
#define SB2U 132                    /* B stride (u32) */
#define G1_AF_WORDS (128 * SA1F)    /* 16896 */
#define G1_AH_WORDS (128 * SAH)     /* 8704 */
#define G1_SMEM_W   (G1_AF_WORDS + G1_AH_WORDS)   /* 25600 u32 = 100 KB */

__global__ __launch_bounds__(256, 2) void k_gemm1(
    const float* __restrict__ emb, const int* __restrict__ eidx) {
    extern __shared__ float sm[];
    float* As = sm;                                   // [128][132] fp32 (phase 1)
    uint32_t* AH = (uint32_t*)sm + G1_AF_WORDS;       // [128][68] packed fp16 pairs
    uint32_t* Bh2 = (uint32_t*)sm;                    // overlays As (phase 2)
    uint32_t* Bl2 = (uint32_t*)sm + 64 * SB2U;
    int t = blockIdx.y;
    const float* embt = emb + (size_t)t * N_ENT * D;
    const int* idxt = eidx + (size_t)t * N_ENT;
    int tid = threadIdx.x;
    int bm = blockIdx.x * 128;
    uint32_t sbase = (uint32_t)__cvta_generic_to_shared(sm);

    // phase 1: stage A fp32 (gathered rows)
#pragma unroll
    for (int i = 0; i < 16; i++) {
        int l = tid + i * 256;
        int row = l >> 5, c4 = l & 31;
        int rg = bm + row;
        int srcr = (rg < N_ENT) ? idxt[rg] : 0;
        cp16(sbase + (uint32_t)(row * SA1F + 4 * c4) * 4, embt + (size_t)srcr * D + 4 * c4);
    }
    CP_COMMIT; CP_WAIT0;
    __syncthreads();

    int lane = tid & 31, wid = tid >> 5;

    // exact fp32 logits from staged rows
    {
        float4 ws4 = ((const float4*)g_was)[lane];
        float4 wd4 = ((const float4*)g_wad)[lane];
        for (int i = 0; i < 16; i++) {
            int row = wid * 16 + i;
            int rg = bm + row;
            if (rg >= N_ENT) break;
            float4 x = *(float4*)&As[row * SA1F + 4 * lane];
            float s = x.x * ws4.x + x.y * ws4.y + x.z * ws4.z + x.w * ws4.w;
            float d = x.x * wd4.x + x.y * wd4.y + x.z * wd4.z + x.w * wd4.w;
#pragma unroll
            for (int off = 16; off; off >>= 1) {
                s += __shfl_xor_sync(0xffffffffu, s, off);
                d += __shfl_xor_sync(0xffffffffu, d, off);
            }
            if (lane == 0) { g_as[t * N_ENT + rg] = s; g_ad[t * N_ENT + rg] = d; }
        }
    }

    // convert A to packed fp16 k-pairs
#pragma unroll
    for (int i = 0; i < 32; i++) {
        int idx = tid + i * 256;           // 8192 pairs
        int row = idx >> 6, kp = idx & 63;
        float2 x = *(const float2*)&As[row * SA1F + 2 * kp];
        AH[row * SAH + kp] = h2pack(x.x, x.y);
    }
    __syncthreads();                       // all reads of As done

    // phase 2: stage B planes into the old As region
#pragma unroll
    for (int i = 0; i < 8; i++) {
        int l = tid + i * 256;
        int row = l >> 5, c8 = l & 31;
        cp16(sbase + (uint32_t)(row * SB2U + c8 * 4) * 4, g_lwh2 + row * 128 + c8 * 4);
        cp16(sbase + (uint32_t)(64 * SB2U + row * SB2U + c8 * 4) * 4, g_lwl2 + row * 128 + c8 * 4);
    }
    CP_COMMIT; CP_WAIT0;
    __syncthreads();

    int wm = (wid & 3) * 32, wn = (wid >> 2) * 64;
    int l4 = lane >> 2, lq = lane & 3;
    float acc[2][8][4];
#pragma unroll
    for (int mt = 0; mt < 2; mt++)
#pragma unroll
        for (int nt = 0; nt < 8; nt++)
#pragma unroll
            for (int q = 0; q < 4; q++) acc[mt][nt][q] = 0.f;

#pragma unroll
    for (int ks = 0; ks < 8; ks++) {
        int kp = ks * 8;
        uint32_t a[2][4];
#pragma unroll
        for (int mt = 0; mt < 2; mt++) {
            int r = wm + mt * 16 + l4;
            a[mt][0] = AH[r * SAH + kp + lq];
            a[mt][1] = AH[(r + 8) * SAH + kp + lq];
            a[mt][2] = AH[r * SAH + kp + lq + 4];
            a[mt][3] = AH[(r + 8) * SAH + kp + lq + 4];
        }
#pragma unroll
        for (int nt = 0; nt < 8; nt++) {
            int cb = wn + nt * 8 + l4;
            uint32_t b0h = Bh2[(kp + lq) * SB2U + cb];
            uint32_t b1h = Bh2[(kp + 4 + lq) * SB2U + cb];
            uint32_t b0l = Bl2[(kp + lq) * SB2U + cb];
            uint32_t b1l = Bl2[(kp + 4 + lq) * SB2U + cb];
#pragma unroll
            for (int mt = 0; mt < 2; mt++) {
                mma16(acc[mt][nt], a[mt], b0h, b1h);
                mma16(acc[mt][nt], a[mt], b0l, b1l);
            }
        }
    }

    // epilogue: direct half2 fragment stores
#pragma unroll
    for (int mt = 0; mt < 2; mt++)
#pragma unroll
        for (int nt = 0; nt < 8; nt++) {
            int r0 = bm + wm + mt * 16 + l4;
            int c = wn + nt * 8 + 2 * lq;
            if (r0 < N_ENT)
                *(uint32_t*)(g_xw + ((size_t)t * N_ENT + r0) * D + c) =
                    h2pack(acc[mt][nt][0], acc[mt][nt][1]);
            int r1 = r0 + 8;
            if (r1 < N_ENT)
                *(uint32_t*)(g_xw + ((size_t)t * N_ENT + r1) * D + c) =
                    h2pack(acc[mt][nt][2], acc[mt][nt][3]);
        }
}

// ================= fused GAT: single-pass softmax+aggregate + bias + LN =================
__global__ void k_gat(const float* __restrict__ conv_bias,
                      const float* __restrict__ gamma_all, const float* __restrict__ beta_all) {
    int t = blockIdx.y;
    int dn = blockIdx.x * 8 + (threadIdx.x >> 5);
    if (dn >= N_ENT) return;
    int lane = threadIdx.x & 31;
    const float* asv = g_as + t * N_ENT;
    float ad = g_ad[t * N_ENT + dn];
    int off0 = g_off[t * N_ENT + dn];
    int off1 = (dn + 1 < N_ENT) ? g_off[t * N_ENT + dn + 1] : E_EDGES;
    const int* csr = g_csr + (size_t)t * E_EDGES;
    const __half* xw = g_xw + (size_t)t * N_ENT * D;

    float ex_self = __expf(leaky(asv[dn] + ad));
    float wsum = ex_self;
    float4 vs = ld_half4(xw + (size_t)dn * D, lane);
    float4 acc = make_float4(ex_self * vs.x, ex_self * vs.y, ex_self * vs.z, ex_self * vs.w);

    for (int j = off0; j < off1; j++) {
        int s = csr[j];
        float e = __expf(leaky(asv[s] + ad));
        float4 v = ld_half4(xw + (size_t)s * D, lane);
        FMA4(acc, e, v);
        wsum += e;
    }
    float inv = 1.f / (wsum + 1e-16f);
    acc.x *= inv; acc.y *= inv; acc.z *= inv; acc.w *= inv;

    float4 cb = ((const float4*)conv_bias)[lane];
    acc.x += cb.x; acc.y += cb.y; acc.z += cb.z; acc.w += cb.w;
    float sum = acc.x + acc.y + acc.z + acc.w;
#pragma unroll
    for (int off = 16; off; off >>= 1) sum += __shfl_xor_sync(0xffffffffu, sum, off);
    float mu = sum * (1.f / D);
    float4 dd = make_float4(acc.x - mu, acc.y - mu, acc.z - mu, acc.w - mu);
    float sq = dd.x * dd.x + dd.y * dd.y + dd.z * dd.z + dd.w * dd.w;
#pragma unroll
    for (int off = 16; off; off >>= 1) sq += __shfl_xor_sync(0xffffffffu, sq, off);
    float invs = rsqrtf(sq * (1.f / D) + LN_EPS);
    float4 gm = ((const float4*)(gamma_all + t * D))[lane];
    float4 bt = ((const float4*)(beta_all + t * D))[lane];
    float4 h;
    h.x = dd.x * invs * gm.x + bt.x;
    h.y = dd.y * invs * gm.y + bt.y;
    h.z = dd.z * invs * gm.z + bt.z;
    h.w = dd.w * invs * gm.w + bt.w;
    st_half4(g_h + ((size_t)t * N_ENT + dn) * D, lane, h);
}

// ================= msg gather into combined buffer (fp16 out) =================
__global__ void k_msg() {
    int t = blockIdx.y;
    int dn = blockIdx.x * 8 + (threadIdx.x >> 5);
    if (dn >= N_TX) return;
    int lane = threadIdx.x & 31;
    int off0 = g_off[t * N_ENT + dn];
    int off1 = (dn + 1 < N_ENT) ? g_off[t * N_ENT + dn + 1] : E_EDGES;
    const int* csr = g_csr + (size_t)t * E_EDGES;
    const __half* h = g_h + (size_t)t * N_ENT * D;
    float4 acc = make_float4(0.f, 0.f, 0.f, 0.f);
    for (int j = off0; j < off1; j++) {
        float4 v = ld_half4(h + (size_t)csr[j] * D, lane);
        acc.x += v.x; acc.y += v.y; acc.z += v.z; acc.w += v.w;
    }
    st_half4(g_comb + (size_t)dn * COMB_STRIDE + t * D, lane, acc);
}

// ================= classifier: h1 (fp16 A + 2-term B mma) fused with h2/h3 =================
#define SA2P 20
#define SBH 136
#define NIT 57
#define H1_A_WORDS   (128 * SA2P)        /* 2560 u32 per stage */
#define H1_B_WORDS   (16 * SBH)          /* 2176 u32 per plane */
#define H1_C_WORDS   (128 * 132)         /* 16896 fl (overlays staging) */
#define H1_WS_OFF    H1_C_WORDS
#define H1_SMEM_W    (H1_WS_OFF + 128 * 64)   /* 25088 words = 100.4 KB */

__device__ __forceinline__ void h1_stage(uint32_t abase, uint32_t bhbase, uint32_t blbase,
                                         int kc, int bm, int tid) {
#pragma unroll
    for (int i = 0; i < 2; i++) {       // A: 128 rows x 4 chunks (16B = 8 halves)
        int l = tid + i * 256;
        int row = l >> 2, c = l & 3;
        int rg = bm + row;
        if (rg >= N_TX) rg = 0;
        cp16(abase + (uint32_t)(row * SA2P + c * 4) * 4,
             g_comb + (size_t)rg * COMB_STRIDE + kc + c * 8);
    }
    int kcp = kc >> 1;
#pragma unroll
    for (int i = 0; i < 2; i++) {       // Bh2/Bl2: 16 rows x 32 chunks
        int l = tid + i * 256;
        int kk = l >> 5, c8 = l & 31;
        cp16(bhbase + (uint32_t)(kk * SBH + c8 * 4) * 4,
             g_w1h2 + (size_t)(kcp + kk) * 128 + c8 * 4);
        cp16(blbase + (uint32_t)(kk * SBH + c8 * 4) * 4,
             g_w1l2 + (size_t)(kcp + kk) * 128 + c8 * 4);
    }
}

__global__ __launch_bounds__(256, 2) void k_h1(
    const float* __restrict__ b1, const float* __restrict__ w2,
    const float* __restrict__ b2, const float* __restrict__ w3,
    const float* __restrict__ b3, float* __restrict__ out) {
    extern __shared__ float sm[];
    int tid = threadIdx.x;
    int bm = blockIdx.x * 128;
    uint32_t sbase = (uint32_t)__cvta_generic_to_shared(sm);
    uint32_t aB[2]  = {sbase, sbase + (uint32_t)H1_A_WORDS * 4};
    uint32_t bhB[2] = {sbase + (uint32_t)(2 * H1_A_WORDS) * 4,
                       sbase + (uint32_t)(2 * H1_A_WORDS + H1_B_WORDS) * 4};
    uint32_t blB[2] = {sbase + (uint32_t)(2 * H1_A_WORDS + 2 * H1_B_WORDS) * 4,
                       sbase + (uint32_t)(2 * H1_A_WORDS + 3 * H1_B_WORDS) * 4};
    const uint32_t* Ap[2] = {(const uint32_t*)sm, (const uint32_t*)sm + H1_A_WORDS};
    const uint32_t* Bhp[2] = {(const uint32_t*)sm + 2 * H1_A_WORDS,
                              (const uint32_t*)sm + 2 * H1_A_WORDS + H1_B_WORDS};
    const uint32_t* Blp[2] = {(const uint32_t*)sm + 2 * H1_A_WORDS + 2 * H1_B_WORDS,
                              (const uint32_t*)sm + 2 * H1_A_WORDS + 3 * H1_B_WORDS};

    // stage Ws (w2) once, into non-overlapping region
    {
        uint32_t wsbase = sbase + (uint32_t)H1_WS_OFF * 4;
#pragma unroll
        for (int i = 0; i < 8; i++) {
            int l = tid + i * 256;      // 2048 chunks of 16B
            cp16(wsbase + (uint32_t)l * 16, w2 + l * 4);
        }
    }

    int lane = tid & 31, wid = tid >> 5;
    int wm = (wid & 3) * 32, wn = (wid >> 2) * 64;
    int l4 = lane >> 2, lq = lane & 3;
    float acc[2][8][4];
#pragma unroll
    for (int mt = 0; mt < 2; mt++)
#pragma unroll
        for (int nt = 0; nt < 8; nt++)
#pragma unroll
            for (int q = 0; q < 4; q++) acc[mt][nt][q] = 0.f;

    h1_stage(aB[0], bhB[0], blB[0], 0, bm, tid);
    CP_COMMIT;

    for (int it = 0; it < NIT; it++) {
        int cur = it & 1;
        CP_WAIT0;
        __syncthreads();
        if (it + 1 < NIT) {
            h1_stage(aB[1 - cur], bhB[1 - cur], blB[1 - cur], (it + 1) * 32, bm, tid);
            CP_COMMIT;
        }
        const uint32_t* Af = Ap[cur];
        const uint32_t* Bhf = Bhp[cur];
        const uint32_t* Blf = Blp[cur];
#pragma unroll
        for (int ks = 0; ks < 2; ks++) {
            int kp = ks * 8;
            uint32_t a[2][4];
#pragma unroll
            for (int mt = 0; mt < 2; mt++) {
                int r = wm + mt * 16 + l4;
                a[mt][0] = Af[r * SA2P + kp + lq];
                a[mt][1] = Af[(r + 8) * SA2P + kp + lq];
                a[mt][2] = Af[r * SA2P + kp + lq + 4];
                a[mt][3] = Af[(r + 8) * SA2P + kp + lq + 4];
            }
#pragma unroll
            for (int nt = 0; nt < 8; nt++) {
                int cb = wn + nt * 8 + l4;
                uint32_t b0h = Bhf[(kp + lq) * SBH + cb];
                uint32_t b1h = Bhf[(kp + 4 + lq) * SBH + cb];
                uint32_t b0l = Blf[(kp + lq) * SBH + cb];
                uint32_t b1l = Blf[(kp + 4 + lq) * SBH + cb];
#pragma unroll
                for (int mt = 0; mt < 2; mt++) {
                    mma16(acc[mt][nt], a[mt], b0h, b1h);
                    mma16(acc[mt][nt], a[mt], b0l, b1l);
                }
            }
        }
        __syncthreads();
    }

    // write bias+relu h1 tile into smem C (overlays staging region)
    float* Cs = sm;
#pragma unroll
    for (int mt = 0; mt < 2; mt++)
#pragma unroll
        for (int nt = 0; nt < 8; nt++) {
            int r = wm + mt * 16 + l4;
            int c = wn + nt * 8 + 2 * lq;
            float2 bb = *(const float2*)(b1 + c);
            Cs[r * 132 + c]           = fmaxf(acc[mt][nt][0] + bb.x, 0.f);
            Cs[r * 132 + c + 1]       = fmaxf(acc[mt][nt][1] + bb.y, 0.f);
            Cs[(r + 8) * 132 + c]     = fmaxf(acc[mt][nt][2] + bb.x, 0.f);
            Cs[(r + 8) * 132 + c + 1] = fmaxf(acc[mt][nt][3] + bb.y, 0.f);
        }
    __syncthreads();

    // fused h2 -> out
    const float* Ws = sm + H1_WS_OFF;
    float2 bb2 = *(const float2*)&b2[lane * 2];
    float2 w3v = *(const float2*)&w3[lane * 2];
    float b3v = b3[0];
    for (int i = 0; i < 16; i++) {
        int lr = wid * 16 + i;
        int r = bm + lr;
        if (r >= N_TX) break;
        float4 x = *(float4*)&Cs[lr * 132 + 4 * lane];
        float xa[4] = {x.x, x.y, x.z, x.w};
        float a0 = 0.f, a1 = 0.f;
#pragma unroll
        for (int k = 0; k < 128; k++) {
            float xk = __shfl_sync(0xffffffffu, xa[k & 3], k >> 2);
            float2 wv = *(const float2*)&Ws[k * 64 + lane * 2];
            a0 += xk * wv.x;
            a1 += xk * wv.y;
        }
        float h0 = fmaxf(a0 + bb2.x, 0.f);
        float h1v = fmaxf(a1 + bb2.y, 0.f);
        float v = h0 * w3v.x + h1v * w3v.y;
#pragma unroll
        for (int off = 16; off; off >>= 1) v += __shfl_xor_sync(0xffffffffu, v, off);
        if (lane == 0) out[r] = v + b3v;
    }
}

// ================= launcher =================
extern "C" void kernel_launch(void* const* d_in, const int* in_sizes, int n_in,
                              void* d_out, int out_size) {
    const float* tx_x      = (const float*)d_in[0];
    const float* emb       = (const float*)d_in[1];
    const float* lin_w     = (const float*)d_in[2];
    const float* att_src   = (const float*)d_in[3];
    const float* att_dst   = (const float*)d_in[4];
    const float* conv_bias = (const float*)d_in[5];
    const float* ln_gamma  = (const float*)d_in[6];
    const float* ln_beta   = (const float*)d_in[7];
    const float* w1        = (const float*)d_in[8];
    const float* b1        = (const float*)d_in[9];
    const float* w2        = (const float*)d_in[10];
    const float* b2        = (const float*)d_in[11];
    const float* w3        = (const float*)d_in[12];
    const float* b3        = (const float*)d_in[13];
    const int* entity_idx  = (const int*)d_in[14];
    const int* edge_src    = (const int*)d_in[15];
    const int* edge_dst    = (const int*)d_in[16];
    float* out = (float*)d_out;

    cudaFuncSetAttribute(k_gemm1, cudaFuncAttributeMaxDynamicSharedMemorySize,
                         G1_SMEM_W * 4);
    cudaFuncSetAttribute(k_h1, cudaFuncAttributeMaxDynamicSharedMemorySize,
                         H1_SMEM_W * 4);

    // (1) weight splits + logit vectors
    k_split_w<<<((COMB_STRIDE / 2) * 128 + 255) / 256, 256>>>(lin_w, w1, att_src, att_dst);
    // (2,3) CSR histogram
    k_zero_cnt<<<(T * N_ENT + 255) / 256, 256>>>();
    { dim3 g((E_EDGES + 255) / 256, T); k_hist<<<g, 256>>>(edge_dst); }
    // (4) gemm1 — profiled launch
    { dim3 g((N_ENT + 127) / 128, T);
      k_gemm1<<<g, 256, G1_SMEM_W * 4>>>(emb, entity_idx); }
    // (5..7) rest of CSR
    { dim3 g(NBLK_SCAN, T); k_scan1<<<g, SCAN_BLK>>>(); }
    { dim3 g(NBLK_SCAN, T); k_scan23<<<g, SCAN_BLK>>>(); }
    { dim3 g((E_EDGES + 255) / 256, T); k_fill<<<g, 256>>>(edge_src, edge_dst); }
    // (8) tx into combined buffer
    k_copytx<<<(N_TX + 7) / 8, 256>>>(tx_x);
    // (9,10) gathers
    { dim3 g((N_ENT + 7) / 8, T); k_gat<<<g, 256>>>(conv_bias, ln_gamma, ln_beta); }
    { dim3 g((N_TX + 7) / 8, T); k_msg<<<g, 256>>>(); }
    // (11) fused classifier
    k_h1<<<(N_TX + 127) / 128, 256, H1_SMEM_W * 4>>>(b1, w2, b2, w3, b3, out);
}